// round 13
// baseline (speedup 1.0000x reference)
#include <cuda_runtime.h>
#include <cuda_bf16.h>
#include <cstdint>

#define S     2048
#define H     16
#define D     64
#define HID   1024
#define KHH   204
#define LCOMP 512
#define KC    716
#define KCPAD 768
#define SCALE 0.125f
#define NKT   64      // 32-wide k sub-tiles per score row
#define LOG1EM8 -18.420680743952367f

#define PA 72   // bf16 pitch, row-major [row][k<=64] tiles
#define PB 136  // bf16 pitch, row-major [k][n<=128] tiles
#define PQ 72   // attn2 smem pitch

// ---------------- device scratch ----------------
__device__ float g_q[S * HID];
__device__ float g_k[S * HID];
__device__ float g_v[S * HID];
__device__ float g_ao[S * HID];
__device__ float g_scores[(size_t)H * S * S];
__device__ float g_pm[(size_t)H * S * NKT];
__device__ float g_pz[(size_t)H * S * NKT];
__device__ float g_rowM[H * S];
__device__ float g_rowZ[H * S];
__device__ float g_logZ[H * S];
__device__ float g_ent[H * S];
__device__ float g_maxa[H * S];
__device__ float g_infl[H * S];
__device__ int   g_hhidx[KHH];
// pre-split bf16 hi/lo K/V cat buffers; padding rows [KC,KCPAD) never written -> stay zero
__device__ __nv_bfloat16 g_kcath[(size_t)H * KCPAD * D];
__device__ __nv_bfloat16 g_kcatl[(size_t)H * KCPAD * D];
__device__ __nv_bfloat16 g_vcath[(size_t)H * KCPAD * D];
__device__ __nv_bfloat16 g_vcatl[(size_t)H * KCPAD * D];

// ---------------- mma.sync helpers ----------------
__device__ __forceinline__ uint32_t smem_u32(const void* p) {
    uint32_t a;
    asm("{ .reg .u64 t; cvta.to.shared.u64 t, %1; cvt.u32.u64 %0, t; }" : "=r"(a) : "l"(p));
    return a;
}
__device__ __forceinline__ void ldmx4(uint32_t* r, uint32_t addr) {
    asm volatile("ldmatrix.sync.aligned.m8n8.x4.shared.b16 {%0,%1,%2,%3}, [%4];"
                 : "=r"(r[0]), "=r"(r[1]), "=r"(r[2]), "=r"(r[3]) : "r"(addr));
}
__device__ __forceinline__ void ldmx4t(uint32_t* r, uint32_t addr) {
    asm volatile("ldmatrix.sync.aligned.m8n8.x4.trans.shared.b16 {%0,%1,%2,%3}, [%4];"
                 : "=r"(r[0]), "=r"(r[1]), "=r"(r[2]), "=r"(r[3]) : "r"(addr));
}
__device__ __forceinline__ void ldmx2(uint32_t* r, uint32_t addr) {
    asm volatile("ldmatrix.sync.aligned.m8n8.x2.shared.b16 {%0,%1}, [%2];"
                 : "=r"(r[0]), "=r"(r[1]) : "r"(addr));
}
__device__ __forceinline__ void ldmx2t(uint32_t* r, uint32_t addr) {
    asm volatile("ldmatrix.sync.aligned.m8n8.x2.trans.shared.b16 {%0,%1}, [%2];"
                 : "=r"(r[0]), "=r"(r[1]) : "r"(addr));
}
__device__ __forceinline__ void mma16816(float* d, const uint32_t* a, const uint32_t* b) {
    asm volatile("mma.sync.aligned.m16n8k16.row.col.f32.bf16.bf16.f32 "
                 "{%0,%1,%2,%3}, {%4,%5,%6,%7}, {%8,%9}, {%0,%1,%2,%3};"
                 : "+f"(d[0]), "+f"(d[1]), "+f"(d[2]), "+f"(d[3])
                 : "r"(a[0]), "r"(a[1]), "r"(a[2]), "r"(a[3]), "r"(b[0]), "r"(b[1]));
}
__device__ __forceinline__ void bsplit(float x, __nv_bfloat16& h, __nv_bfloat16& l) {
    h = __float2bfloat16(x);
    l = __float2bfloat16(x - __bfloat162float(h));
}
__device__ __forceinline__ uint32_t bpack(__nv_bfloat16 a, __nv_bfloat16 b) {
    __nv_bfloat162 p = __halves2bfloat162(a, b);
    return *(uint32_t*)&p;
}
__device__ __forceinline__ void split4(float4 v, uint2& hh, uint2& ll) {
    __nv_bfloat16 h0, h1, h2, h3, l0, l1, l2, l3;
    bsplit(v.x, h0, l0); bsplit(v.y, h1, l1);
    bsplit(v.z, h2, l2); bsplit(v.w, h3, l3);
    hh = make_uint2(bpack(h0, h1), bpack(h2, h3));
    ll = make_uint2(bpack(l0, l1), bpack(l2, l3));
}
__device__ __forceinline__ void packhl(float a, float b, uint32_t& hh, uint32_t& ll) {
    __nv_bfloat16 ha, la, hb, lb;
    bsplit(a, ha, la); bsplit(b, hb, lb);
    hh = bpack(ha, hb); ll = bpack(la, lb);
}

// warp compute for one 64-K chunk (gemm/scores kernels) — R11 version (x2 B loads)
template <bool BKN>
__device__ __forceinline__ void mma_chunk(uint32_t ahB, uint32_t alB,
                                          uint32_t bhB, uint32_t blB,
                                          int wm, int wn, int lane,
                                          float acc[4][4][4]) {
#pragma unroll
    for (int ks = 0; ks < 4; ks++) {
        uint32_t bh[4][2], bl[4][2];
#pragma unroll
        for (int ni = 0; ni < 4; ni++) {
            uint32_t off;
            if (BKN)
                off = ((uint32_t)(ks * 16 + (lane & 7) + ((lane >> 3) & 1) * 8) * PB
                       + wn * 32 + ni * 8) * 2;
            else
                off = ((uint32_t)(wn * 32 + ni * 8 + (lane & 7)) * PA
                       + ks * 16 + ((lane >> 3) & 1) * 8) * 2;
            if (BKN) { ldmx2t(bh[ni], bhB + off); ldmx2t(bl[ni], blB + off); }
            else     { ldmx2 (bh[ni], bhB + off); ldmx2 (bl[ni], blB + off); }
        }
        uint32_t a[4][4];
        uint32_t aoff[4];
#pragma unroll
        for (int mi = 0; mi < 4; mi++) {
            aoff[mi] = ((uint32_t)(wm * 64 + mi * 16 + (lane & 15)) * PA
                        + ks * 16 + ((lane >> 4) << 3)) * 2;
            ldmx4(a[mi], ahB + aoff[mi]);
        }
#pragma unroll
        for (int mi = 0; mi < 4; mi++)
#pragma unroll
            for (int ni = 0; ni < 4; ni++) {
                mma16816(acc[mi][ni], a[mi], bh[ni]);
                mma16816(acc[mi][ni], a[mi], bl[ni]);
            }
#pragma unroll
        for (int mi = 0; mi < 4; mi++) ldmx4(a[mi], alB + aoff[mi]);
#pragma unroll
        for (int mi = 0; mi < 4; mi++)
#pragma unroll
            for (int ni = 0; ni < 4; ni++) mma16816(acc[mi][ni], a[mi], bh[ni]);
    }
}

#define GEMM_SMEM  (128 * PA * 2 * 2 + 64 * PB * 2 * 2)
#define SCORE_SMEM (128 * PA * 2 * 4)
#define ATTN2_SMEM ((2 * 64 + 4 * 128) * PQ * 2)

// ---------------- bf16x3 mma GEMM ----------------
__device__ __forceinline__ void gemm_mma_body(const float* __restrict__ A,
                                              const float* __restrict__ Bm,
                                              float* __restrict__ C, int nch) {
    extern __shared__ char dsm[];
    char* Ah = dsm;
    char* Al = Ah + 128 * PA * 2;
    char* Bh = Al + 128 * PA * 2;
    char* Bl = Bh + 64 * PB * 2;
    uint32_t ahB = smem_u32(Ah), alB = smem_u32(Al);
    uint32_t bhB = smem_u32(Bh), blB = smem_u32(Bl);
    int tid = threadIdx.x;
    int wid = tid >> 5, lane = tid & 31;
    int wm = wid >> 2, wn = wid & 3;
    int crow = blockIdx.y * 128, ccol = blockIdx.x * 128;

    float acc[4][4][4];
#pragma unroll
    for (int mi = 0; mi < 4; mi++)
#pragma unroll
        for (int ni = 0; ni < 4; ni++)
#pragma unroll
            for (int e = 0; e < 4; e++) acc[mi][ni][e] = 0.f;

    for (int ch = 0; ch < nch; ch++) {
        int k0 = ch * 64;
        __syncthreads();
#pragma unroll
        for (int i = 0; i < 8; i++) {
            int idx = tid + i * 256;
            int row = idx >> 4, c4 = (idx & 15) * 4;
            float4 v = *(const float4*)&A[(size_t)(crow + row) * HID + k0 + c4];
            uint2 hh, ll;
            split4(v, hh, ll);
            *(uint2*)(Ah + ((uint32_t)row * PA + c4) * 2) = hh;
            *(uint2*)(Al + ((uint32_t)row * PA + c4) * 2) = ll;
        }
#pragma unroll
        for (int i = 0; i < 8; i++) {
            int idx = tid + i * 256;
            int kr = idx >> 5, n4 = (idx & 31) * 4;
            float4 v = *(const float4*)&Bm[(size_t)(k0 + kr) * HID + ccol + n4];
            uint2 hh, ll;
            split4(v, hh, ll);
            *(uint2*)(Bh + ((uint32_t)kr * PB + n4) * 2) = hh;
            *(uint2*)(Bl + ((uint32_t)kr * PB + n4) * 2) = ll;
        }
        __syncthreads();
        mma_chunk<true>(ahB, alB, bhB, blB, wm, wn, lane, acc);
    }

    int quad = lane >> 2, qq = lane & 3;
#pragma unroll
    for (int mi = 0; mi < 4; mi++)
#pragma unroll
        for (int ni = 0; ni < 4; ni++) {
            int r = crow + wm * 64 + mi * 16 + quad;
            int c = ccol + wn * 32 + ni * 8 + qq * 2;
            *(float2*)&C[(size_t)r * HID + c] = make_float2(acc[mi][ni][0], acc[mi][ni][1]);
            *(float2*)&C[(size_t)(r + 8) * HID + c] = make_float2(acc[mi][ni][2], acc[mi][ni][3]);
        }
}

__global__ __launch_bounds__(256) void qkv_mma_kernel(const float* __restrict__ x,
                                                      const float* __restrict__ wq,
                                                      const float* __restrict__ wk,
                                                      const float* __restrict__ wv,
                                                      int zbase) {
    int z = zbase + blockIdx.z;
    const float* B = z == 0 ? wq : (z == 1 ? wk : wv);
    float* C = z == 0 ? g_q : (z == 1 ? g_k : g_v);
    gemm_mma_body(x, B, C, 16);
}

__global__ __launch_bounds__(256) void out_mma_kernel(const float* __restrict__ wo,
                                                      float* __restrict__ out) {
    gemm_mma_body(g_ao, wo, out, 16);
}

// ---------------- scores: bf16x3 mma Q@K^T + fused row-stat partials ----------------
__global__ __launch_bounds__(256) void scores_mma_kernel() {
    extern __shared__ char dsm[];
    char* Ah = dsm;
    char* Al = Ah + 128 * PA * 2;
    char* Bh = Al + 128 * PA * 2;
    char* Bl = Bh + 128 * PA * 2;
    uint32_t ahB = smem_u32(Ah), alB = smem_u32(Al);
    uint32_t bhB = smem_u32(Bh), blB = smem_u32(Bl);
    int tid = threadIdx.x;
    int wid = tid >> 5, lane = tid & 31;
    int wm = wid >> 2, wn = wid & 3;
    int h = blockIdx.z, q0 = blockIdx.y * 128, k0 = blockIdx.x * 128;
    const float* Aq = g_q + h * D;
    const float* Bk = g_k + h * D;

#pragma unroll
    for (int i = 0; i < 8; i++) {
        int idx = tid + i * 256;
        int row = idx >> 4, c4 = (idx & 15) * 4;
        uint32_t so = ((uint32_t)row * PA + c4) * 2;
        uint2 hh, ll;
        split4(*(const float4*)&Aq[(size_t)(q0 + row) * HID + c4], hh, ll);
        *(uint2*)(Ah + so) = hh;
        *(uint2*)(Al + so) = ll;
        split4(*(const float4*)&Bk[(size_t)(k0 + row) * HID + c4], hh, ll);
        *(uint2*)(Bh + so) = hh;
        *(uint2*)(Bl + so) = ll;
    }
    __syncthreads();

    float acc[4][4][4];
#pragma unroll
    for (int mi = 0; mi < 4; mi++)
#pragma unroll
        for (int ni = 0; ni < 4; ni++)
#pragma unroll
            for (int e = 0; e < 4; e++) acc[mi][ni][e] = 0.f;

    mma_chunk<false>(ahB, alB, bhB, blB, wm, wn, lane, acc);

#pragma unroll
    for (int mi = 0; mi < 4; mi++)
#pragma unroll
        for (int ni = 0; ni < 4; ni++)
#pragma unroll
            for (int e = 0; e < 4; e++) acc[mi][ni][e] *= SCALE;

    float* sc = g_scores + (size_t)h * S * S;
    int quad = lane >> 2, qq = lane & 3;
#pragma unroll
    for (int mi = 0; mi < 4; mi++)
#pragma unroll
        for (int ni = 0; ni < 4; ni++) {
            int r = q0 + wm * 64 + mi * 16 + quad;
            int c = k0 + wn * 32 + ni * 8 + qq * 2;
            *(float2*)&sc[(size_t)r * S + c] = make_float2(acc[mi][ni][0], acc[mi][ni][1]);
            *(float2*)&sc[(size_t)(r + 8) * S + c] = make_float2(acc[mi][ni][2], acc[mi][ni][3]);
        }

    int tile = blockIdx.x * 4 + wn;
#pragma unroll
    for (int mi = 0; mi < 4; mi++) {
        float m0 = -1e30f, m1 = -1e30f;
#pragma unroll
        for (int ni = 0; ni < 4; ni++) {
            m0 = fmaxf(m0, fmaxf(acc[mi][ni][0], acc[mi][ni][1]));
            m1 = fmaxf(m1, fmaxf(acc[mi][ni][2], acc[mi][ni][3]));
        }
        m0 = fmaxf(m0, __shfl_xor_sync(0xffffffffu, m0, 1));
        m0 = fmaxf(m0, __shfl_xor_sync(0xffffffffu, m0, 2));
        m1 = fmaxf(m1, __shfl_xor_sync(0xffffffffu, m1, 1));
        m1 = fmaxf(m1, __shfl_xor_sync(0xffffffffu, m1, 2));
        float z0 = 0.f, z1 = 0.f;
#pragma unroll
        for (int ni = 0; ni < 4; ni++) {
            z0 += __expf(acc[mi][ni][0] - m0) + __expf(acc[mi][ni][1] - m0);
            z1 += __expf(acc[mi][ni][2] - m1) + __expf(acc[mi][ni][3] - m1);
        }
        z0 += __shfl_xor_sync(0xffffffffu, z0, 1);
        z0 += __shfl_xor_sync(0xffffffffu, z0, 2);
        z1 += __shfl_xor_sync(0xffffffffu, z1, 1);
        z1 += __shfl_xor_sync(0xffffffffu, z1, 2);
        if (qq == 0) {
            int r = q0 + wm * 64 + mi * 16 + quad;
            size_t p0 = (size_t)(h * S + r) * NKT + tile;
            size_t p1 = (size_t)(h * S + r + 8) * NKT + tile;
            g_pm[p0] = m0; g_pz[p0] = z0;
            g_pm[p1] = m1; g_pz[p1] = z1;
        }
    }
}

// ---------------- combine partials (64 per row) ----------------
__global__ __launch_bounds__(256) void combine_kernel() {
    int row  = blockIdx.x * 8 + (threadIdx.x >> 5);
    int lane = threadIdx.x & 31;
    float pm0 = g_pm[(size_t)row * NKT + lane];
    float pz0 = g_pz[(size_t)row * NKT + lane];
    float pm1 = g_pm[(size_t)row * NKT + 32 + lane];
    float pz1 = g_pz[(size_t)row * NKT + 32 + lane];
    float m = fmaxf(pm0, pm1);
#pragma unroll
    for (int o = 16; o; o >>= 1) m = fmaxf(m, __shfl_xor_sync(0xffffffffu, m, o));
    float z = __expf(pm0 - m) * pz0 + __expf(pm1 - m) * pz1;
#pragma unroll
    for (int o = 16; o; o >>= 1) z += __shfl_xor_sync(0xffffffffu, z, o);
    if (lane == 0) {
        float rz = 1.0f / z;
        g_rowM[row] = m;
        g_rowZ[row] = rz;
        g_logZ[row] = __logf(z);
        g_maxa[row] = rz;
    }
}

// ---------------- fused entropy + influence ----------------
__global__ __launch_bounds__(256) void stats_kernel() {
    int h  = blockIdx.z;
    int q0 = blockIdx.y * 128;
    int k0 = blockIdx.x * 128;
    int tid = threadIdx.x;
    int wid = tid >> 5, lane = tid & 31;
    __shared__ float wcol[8][128];

    const float* sc = g_scores + (size_t)h * S * S;
    float c0 = 0.f, c1 = 0.f, c2 = 0.f, c3 = 0.f;

#pragma unroll 4
    for (int r = 0; r < 16; r++) {
        int row = q0 + wid * 16 + r;
        float m  = g_rowM[h * S + row];
        float rz = g_rowZ[h * S + row];
        float lz = g_logZ[h * S + row];
        float4 v = *(const float4*)&sc[(size_t)row * S + k0 + lane * 4];
        float s0 = v.x - m, s1 = v.y - m, s2 = v.z - m, s3 = v.w - m;
        float p0 = __expf(s0) * rz, p1 = __expf(s1) * rz;
        float p2 = __expf(s2) * rz, p3 = __expf(s3) * rz;
        c0 += p0; c1 += p1; c2 += p2; c3 += p3;
        float t0 = p0 * ((p0 >= 1e-8f) ? (s0 - lz) : LOG1EM8);
        float t1 = p1 * ((p1 >= 1e-8f) ? (s1 - lz) : LOG1EM8);
        float t2 = p2 * ((p2 >= 1e-8f) ? (s2 - lz) : LOG1EM8);
        float t3 = p3 * ((p3 >= 1e-8f) ? (s3 - lz) : LOG1EM8);
        float e = t0 + t1 + t2 + t3;
#pragma unroll
        for (int o = 16; o; o >>= 1) e += __shfl_xor_sync(0xffffffffu, e, o);
        if (lane == 0) atomicAdd(&g_ent[h * S + row], e);
    }
    *(float4*)&wcol[wid][lane * 4] = make_float4(c0, c1, c2, c3);
    __syncthreads();
    if (tid < 128) {
        float s = 0.f;
#pragma unroll
        for (int w = 0; w < 8; w++) s += wcol[w][tid];
        atomicAdd(&g_infl[h * S + k0 + tid], s);
    }
}

// ---------------- importance + top-204 (single block, bit-identical math) ----------------
__global__ __launch_bounds__(1024) void imptopk_kernel() {
    __shared__ float imp[S];
    int tid = threadIdx.x;
    for (int s = tid; s < S; s += 1024) {
        float a = 0.f;
        for (int h = 0; h < H; h++)
            a += 0.4f * g_ent[h * S + s]
               + 0.3f * g_maxa[h * S + s] + 0.3f * g_infl[h * S + s];
        imp[s] = a * (1.0f / H);
    }
    __syncthreads();
    for (int i = tid; i < S; i += 1024) {
        float vi = imp[i];
        int r = 0;
        for (int j = 0; j < S; j++) {
            float vj = imp[j];
            r += (vj > vi) || (vj == vi && j < i);
        }
        if (r < KHH) g_hhidx[r] = i;
    }
}

// ---------------- norm-softmax-weighted 4:1 compression (writes bf16 hi/lo) ----------------
__global__ __launch_bounds__(256) void compress_kernel() {
    int h = blockIdx.x;
    int which = blockIdx.y;
    const float* src = which ? g_v : g_k;
    __nv_bfloat16* dsth = (which ? g_vcath : g_kcath) + ((size_t)h * KCPAD + KHH) * D;
    __nv_bfloat16* dstl = (which ? g_vcatl : g_kcatl) + ((size_t)h * KCPAD + KHH) * D;
    __shared__ float w[S];
    __shared__ float gs[LCOMP];
    __shared__ float red[256];
    int tid = threadIdx.x;

    for (int s = tid; s < S; s += 256) {
        const float* rp = src + (size_t)s * HID + h * D;
        float a = 0.f;
#pragma unroll
        for (int dd = 0; dd < 64; dd += 4) {
            float4 xv = *(const float4*)&rp[dd];
            a += xv.x * xv.x + xv.y * xv.y + xv.z * xv.z + xv.w * xv.w;
        }
        w[s] = sqrtf(a);
    }
    __syncthreads();
    float lm = -1e30f;
    for (int s = tid; s < S; s += 256) lm = fmaxf(lm, w[s]);
    red[tid] = lm; __syncthreads();
    for (int o = 128; o; o >>= 1) { if (tid < o) red[tid] = fmaxf(red[tid], red[tid + o]); __syncthreads(); }
    float m = red[0]; __syncthreads();
    float lz = 0.f;
    for (int s = tid; s < S; s += 256) { float e = __expf(w[s] - m); w[s] = e; lz += e; }
    red[tid] = lz; __syncthreads();
    for (int o = 128; o; o >>= 1) { if (tid < o) red[tid] += red[tid + o]; __syncthreads(); }
    float rz = 1.0f / red[0]; __syncthreads();
    for (int s = tid; s < S; s += 256) w[s] *= rz;
    __syncthreads();
    for (int l = tid; l < LCOMP; l += 256)
        gs[l] = w[4 * l] + w[4 * l + 1] + w[4 * l + 2] + w[4 * l + 3];
    __syncthreads();
    for (int idx = tid; idx < LCOMP * D; idx += 256) {
        int l  = idx >> 6;
        int dd = idx & 63;
        const float* rp = src + (size_t)(4 * l) * HID + h * D + dd;
        float num = w[4 * l] * rp[0] + w[4 * l + 1] * rp[HID] +
                    w[4 * l + 2] * rp[2 * HID] + w[4 * l + 3] * rp[3 * HID];
        float val = num / (gs[l] + 1e-8f);
        __nv_bfloat16 hb, lb;
        bsplit(val, hb, lb);
        dsth[(size_t)l * D + dd] = hb;
        dstl[(size_t)l * D + dd] = lb;
    }
}

__global__ void gather_kernel() {
    int idx = blockIdx.x * 256 + threadIdx.x;
    if (idx >= H * KHH * D) return;
    int d = idx & 63;
    int i = (idx >> 6) % KHH;
    int h = idx / (KHH * D);
    int s = g_hhidx[i];
    size_t dst = ((size_t)h * KCPAD + i) * D + d;
    size_t srcp = (size_t)s * HID + h * D + d;
    __nv_bfloat16 hb, lb;
    bsplit(g_k[srcp], hb, lb);
    g_kcath[dst] = hb;
    g_kcatl[dst] = lb;
    bsplit(g_v[srcp], hb, lb);
    g_vcath[dst] = hb;
    g_vcatl[dst] = lb;
}

// ---------------- attn2 on tensor pipe: 64 queries / block, 2 blocks/SM ----------------
__global__ __launch_bounds__(128, 2) void attn2_mma_kernel() {
    extern __shared__ char dsm[];
    char* Qh = dsm;                       // [64][PQ] bf16
    char* Ql = Qh + 64 * PQ * 2;
    char* Kh = Ql + 64 * PQ * 2;          // [128 keys][PQ d]
    char* Kl = Kh + 128 * PQ * 2;
    char* Vh = Kl + 128 * PQ * 2;
    char* Vl = Vh + 128 * PQ * 2;
    uint32_t qhB = smem_u32(Qh), qlB = smem_u32(Ql);
    uint32_t khB = smem_u32(Kh), klB = smem_u32(Kl);
    uint32_t vhB = smem_u32(Vh), vlB = smem_u32(Vl);
    int tid = threadIdx.x;
    int wid = tid >> 5, lane = tid & 31;
    int quad = lane >> 2, qq = lane & 3;
    int h = blockIdx.y, q0 = blockIdx.x * 64;

    // stage Q (hi/lo) once: 64 rows
#pragma unroll
    for (int i = 0; i < 8; i++) {
        int idx = tid + i * 128;
        int row = idx >> 4, c4 = (idx & 15) * 4;
        uint2 hh, ll;
        split4(*(const float4*)&g_q[(size_t)(q0 + row) * HID + h * D + c4], hh, ll);
        *(uint2*)(Qh + ((uint32_t)row * PQ + c4) * 2) = hh;
        *(uint2*)(Ql + ((uint32_t)row * PQ + c4) * 2) = ll;
    }
    const __nv_bfloat16* kh = g_kcath + (size_t)h * KCPAD * D;
    const __nv_bfloat16* kl = g_kcatl + (size_t)h * KCPAD * D;
    const __nv_bfloat16* vh = g_vcath + (size_t)h * KCPAD * D;
    const __nv_bfloat16* vl = g_vcatl + (size_t)h * KCPAD * D;

    float oacc[8][4];
#pragma unroll
    for (int ni = 0; ni < 8; ni++)
#pragma unroll
        for (int e = 0; e < 4; e++) oacc[ni][e] = 0.f;
    float m_run0 = -1e30f, m_run1 = -1e30f, z_run0 = 0.f, z_run1 = 0.f;

    for (int kt = 0; kt < KCPAD; kt += 128) {
        __syncthreads();
        // stage K,V chunk (pre-split bf16, pure copies): 128 rows
#pragma unroll
        for (int i = 0; i < 16; i++) {
            int idx = tid + i * 128;
            int row = idx >> 4, c4 = (idx & 15) * 4;
            uint32_t so = ((uint32_t)row * PQ + c4) * 2;
            size_t go = (size_t)(kt + row) * D + c4;
            *(uint2*)(Kh + so) = *(const uint2*)&kh[go];
            *(uint2*)(Kl + so) = *(const uint2*)&kl[go];
            *(uint2*)(Vh + so) = *(const uint2*)&vh[go];
            *(uint2*)(Vl + so) = *(const uint2*)&vl[go];
        }
        __syncthreads();

        // Q frags for this warp's 16 rows
        uint32_t qfh[4][4], qfl[4][4];
#pragma unroll
        for (int ks = 0; ks < 4; ks++) {
            uint32_t aoff = ((uint32_t)(wid * 16 + (lane & 15)) * PQ
                             + ks * 16 + ((lane >> 4) << 3)) * 2;
            ldmx4(qfh[ks], qhB + aoff);
            ldmx4(qfl[ks], qlB + aoff);
        }

        // S = Q @ K^T  (16 x 128)
        float sacc[16][4];
#pragma unroll
        for (int ni = 0; ni < 16; ni++)
#pragma unroll
            for (int e = 0; e < 4; e++) sacc[ni][e] = 0.f;
#pragma unroll
        for (int ks = 0; ks < 4; ks++) {
#pragma unroll
            for (int nj = 0; nj < 8; nj++) {
                uint32_t part = lane >> 3;
                uint32_t boff = ((uint32_t)(nj * 16 + (part >> 1) * 8 + (lane & 7)) * PQ
                                 + ks * 16 + (part & 1) * 8) * 2;
                uint32_t bh[4], bl[4];
                ldmx4(bh, khB + boff);
                ldmx4(bl, klB + boff);
                mma16816(sacc[nj * 2],     qfh[ks], bh);
                mma16816(sacc[nj * 2],     qfh[ks], bl);
                mma16816(sacc[nj * 2],     qfl[ks], bh);
                mma16816(sacc[nj * 2 + 1], qfh[ks], bh + 2);
                mma16816(sacc[nj * 2 + 1], qfh[ks], bl + 2);
                mma16816(sacc[nj * 2 + 1], qfl[ks], bh + 2);
            }
        }

        // scale + mask
#pragma unroll
        for (int ni = 0; ni < 16; ni++) {
            int cg = kt + ni * 8 + qq * 2;
            bool ok0 = cg < KC, ok1 = (cg + 1) < KC;
            sacc[ni][0] = ok0 ? sacc[ni][0] * SCALE : -1e30f;
            sacc[ni][1] = ok1 ? sacc[ni][1] * SCALE : -1e30f;
            sacc[ni][2] = ok0 ? sacc[ni][2] * SCALE : -1e30f;
            sacc[ni][3] = ok1 ? sacc[ni][3] * SCALE : -1e30f;
        }
        // online softmax (rows quad, quad+8)
        float cm0 = -1e30f, cm1 = -1e30f;
#pragma unroll
        for (int ni = 0; ni < 16; ni++) {
            cm0 = fmaxf(cm0, fmaxf(sacc[ni][0], sacc[ni][1]));
            cm1 = fmaxf(cm1, fmaxf(sacc[ni][2], sacc[ni][3]));
        }
        cm0 = fmaxf(cm0, __shfl_xor_sync(0xffffffffu, cm0, 1));
        cm0 = fmaxf(cm0, __shfl_xor_sync(0xffffffffu, cm0, 2));
        cm1 = fmaxf(cm1, __shfl_xor_sync(0xffffffffu, cm1, 1));
        cm1 = fmaxf(cm1, __shfl_xor_sync(0xffffffffu, cm1, 2));
        float mn0 = fmaxf(m_run0, cm0), mn1 = fmaxf(m_run1, cm1);
        float fac0 = __expf(m_run0 - mn0), fac1 = __expf(m_run1 - mn1);
        m_run0 = mn0; m_run1 = mn1;
        float zs0 = 0.f, zs1 = 0.f;
#pragma unroll
        for (int ni = 0; ni < 16; ni++) {
            sacc[ni][0] = __expf(sacc[ni][0] - mn0);
            sacc[ni][1] = __expf(sacc[ni][1] - mn0);
            sacc[ni][2] = __expf(sacc[ni][2] - mn1);
            sacc[ni][3] = __expf(sacc[ni][3] - mn1);
            zs0 += sacc[ni][0] + sacc[ni][1];
            zs1 += sacc[ni][2] + sacc[ni][3];
        }
        zs0 += __shfl_xor_sync(0xffffffffu, zs0, 1);
        zs0 += __shfl_xor_sync(0xffffffffu, zs0, 2);
        zs1 += __shfl_xor_sync(0xffffffffu, zs1, 1);
        zs1 += __shfl_xor_sync(0xffffffffu, zs1, 2);
        z_run0 = z_run0 * fac0 + zs0;
        z_run1 = z_run1 * fac1 + zs1;
#pragma unroll
        for (int ni = 0; ni < 8; ni++) {
            oacc[ni][0] *= fac0; oacc[ni][1] *= fac0;
            oacc[ni][2] *= fac1; oacc[ni][3] *= fac1;
        }

        // P @ V : P frags from C frags in registers (hi/lo)
#pragma unroll
        for (int ks = 0; ks < 8; ks++) {
            uint32_t ph[4], pl[4];
            packhl(sacc[2 * ks][0],     sacc[2 * ks][1],     ph[0], pl[0]);
            packhl(sacc[2 * ks][2],     sacc[2 * ks][3],     ph[1], pl[1]);
            packhl(sacc[2 * ks + 1][0], sacc[2 * ks + 1][1], ph[2], pl[2]);
            packhl(sacc[2 * ks + 1][2], sacc[2 * ks + 1][3], ph[3], pl[3]);
#pragma unroll
            for (int nj = 0; nj < 4; nj++) {
                uint32_t part = lane >> 3;
                uint32_t boff = ((uint32_t)(ks * 16 + (part & 1) * 8 + (lane & 7)) * PQ
                                 + nj * 16 + (part >> 1) * 8) * 2;
                uint32_t vhf[4], vlf[4];
                ldmx4t(vhf, vhB + boff);
                ldmx4t(vlf, vlB + boff);
                mma16816(oacc[nj * 2],     ph, vhf);
                mma16816(oacc[nj * 2],     ph, vlf);
                mma16816(oacc[nj * 2],     pl, vhf);
                mma16816(oacc[nj * 2 + 1], ph, vhf + 2);
                mma16816(oacc[nj * 2 + 1], ph, vlf + 2);
                mma16816(oacc[nj * 2 + 1], pl, vhf + 2);
            }
        }
    }

    float rz0 = 1.0f / z_run0, rz1 = 1.0f / z_run1;
    int r0 = q0 + wid * 16 + quad;
#pragma unroll
    for (int ni = 0; ni < 8; ni++) {
        int c = h * D + ni * 8 + qq * 2;
        *(float2*)&g_ao[(size_t)r0 * HID + c] =
            make_float2(oacc[ni][0] * rz0, oacc[ni][1] * rz0);
        *(float2*)&g_ao[(size_t)(r0 + 8) * HID + c] =
            make_float2(oacc[ni][2] * rz1, oacc[ni][3] * rz1);
    }
}

// ---------------- host ----------------
extern "C" void kernel_launch(void* const* d_in, const int* in_sizes, int n_in,
                              void* d_out, int out_size) {
    const float* x  = (const float*)d_in[0];
    const float* wq = (const float*)d_in[1];
    const float* wk = (const float*)d_in[2];
    const float* wv = (const float*)d_in[3];
    const float* wo = (const float*)d_in[4];
    float* out = (float*)d_out;

    static bool init_done = false;
    static void* ent_addr = nullptr;
    static void* infl_addr = nullptr;
    static cudaStream_t s2;
    static cudaEvent_t evK, evB;
    if (!init_done) {
        cudaFuncSetAttribute(attn2_mma_kernel,
                             cudaFuncAttributeMaxDynamicSharedMemorySize, ATTN2_SMEM);
        cudaFuncSetAttribute(qkv_mma_kernel,
                             cudaFuncAttributeMaxDynamicSharedMemorySize, GEMM_SMEM);
        cudaFuncSetAttribute(out_mma_kernel,
                             cudaFuncAttributeMaxDynamicSharedMemorySize, GEMM_SMEM);
        cudaFuncSetAttribute(scores_mma_kernel,
                             cudaFuncAttributeMaxDynamicSharedMemorySize, SCORE_SMEM);
        cudaGetSymbolAddress(&ent_addr, g_ent);
        cudaGetSymbolAddress(&infl_addr, g_infl);
        cudaStreamCreateWithFlags(&s2, cudaStreamNonBlocking);
        cudaEventCreateWithFlags(&evK, cudaEventDisableTiming);
        cudaEventCreateWithFlags(&evB, cudaEventDisableTiming);
        init_done = true;
    }

    cudaMemsetAsync(ent_addr, 0, H * S * sizeof(float));
    cudaMemsetAsync(infl_addr, 0, H * S * sizeof(float));

    // side stream: V projection (depends only on x, wv) — starts immediately
    qkv_mma_kernel<<<dim3(8, 16, 1), 256, GEMM_SMEM, s2>>>(x, wq, wk, wv, 2);

    // main stream: Q,K projections
    qkv_mma_kernel<<<dim3(8, 16, 2), 256, GEMM_SMEM>>>(x, wq, wk, wv, 0);
    cudaEventRecord(evK, 0);

    // side stream: compression needs g_k (from main) and g_v (same stream)
    cudaStreamWaitEvent(s2, evK, 0);
    compress_kernel<<<dim3(16, 2), 256, 0, s2>>>();
    cudaEventRecord(evB, s2);

    // main stream: heavy-hitter statistics chain (needs only Q,K)
    scores_mma_kernel<<<dim3(16, 16, 16), 256, SCORE_SMEM>>>();
    combine_kernel<<<(H * S) / 8, 256>>>();
    stats_kernel<<<dim3(16, 16, 16), 256>>>();
    imptopk_kernel<<<1, 1024>>>();

    // join: gather needs topk + K,V; attn2 needs kcat/vcat + Q
    cudaStreamWaitEvent(0, evB, 0);
    gather_kernel<<<(H * KHH * D + 255) / 256, 256>>>();
    attn2_mma_kernel<<<dim3(S / 64, H), 128, ATTN2_SMEM>>>();
    out_mma_kernel<<<dim3(8, 16), 256, GEMM_SMEM>>>(wo, out);
}

// round 14
// speedup vs baseline: 1.1270x; 1.1270x over previous
#include <cuda_runtime.h>
#include <cuda_bf16.h>
#include <cstdint>

#define S     2048
#define H     16
#define D     64
#define HID   1024
#define KHH   204
#define LCOMP 512
#define KC    716
#define KCPAD 768
#define SCALE 0.125f
#define NKT   64      // 32-wide k sub-tiles per score row
#define LOG1EM8 -18.420680743952367f

#define PA 72   // bf16 pitch, row-major [row][k<=64] tiles
#define PB 136  // bf16 pitch, row-major [k][n<=128] tiles
#define PQ 72   // attn2 smem pitch

// ---------------- device scratch ----------------
__device__ float g_q[S * HID];
__device__ float g_k[S * HID];
__device__ float g_v[S * HID];
__device__ float g_ao[S * HID];
__device__ float g_scores[(size_t)H * S * S];
__device__ float g_pm[(size_t)H * S * NKT];
__device__ float g_pz[(size_t)H * S * NKT];
__device__ float g_rowM[H * S];
__device__ float g_rowZ[H * S];
__device__ float g_logZ[H * S];
__device__ float g_ent[H * S];
__device__ float g_maxa[H * S];
__device__ float g_infl[H * S];
__device__ float g_imp[S];
__device__ int   g_hhidx[KHH];
__device__ float g_kcat[(size_t)H * KCPAD * D];
__device__ float g_vcat[(size_t)H * KCPAD * D];

// ---------------- mma.sync helpers ----------------
__device__ __forceinline__ uint32_t smem_u32(const void* p) {
    uint32_t a;
    asm("{ .reg .u64 t; cvta.to.shared.u64 t, %1; cvt.u32.u64 %0, t; }" : "=r"(a) : "l"(p));
    return a;
}
__device__ __forceinline__ void ldmx4(uint32_t* r, uint32_t addr) {
    asm volatile("ldmatrix.sync.aligned.m8n8.x4.shared.b16 {%0,%1,%2,%3}, [%4];"
                 : "=r"(r[0]), "=r"(r[1]), "=r"(r[2]), "=r"(r[3]) : "r"(addr));
}
__device__ __forceinline__ void ldmx4t(uint32_t* r, uint32_t addr) {
    asm volatile("ldmatrix.sync.aligned.m8n8.x4.trans.shared.b16 {%0,%1,%2,%3}, [%4];"
                 : "=r"(r[0]), "=r"(r[1]), "=r"(r[2]), "=r"(r[3]) : "r"(addr));
}
__device__ __forceinline__ void ldmx2(uint32_t* r, uint32_t addr) {
    asm volatile("ldmatrix.sync.aligned.m8n8.x2.shared.b16 {%0,%1}, [%2];"
                 : "=r"(r[0]), "=r"(r[1]) : "r"(addr));
}
__device__ __forceinline__ void ldmx2t(uint32_t* r, uint32_t addr) {
    asm volatile("ldmatrix.sync.aligned.m8n8.x2.trans.shared.b16 {%0,%1}, [%2];"
                 : "=r"(r[0]), "=r"(r[1]) : "r"(addr));
}
__device__ __forceinline__ void mma16816(float* d, const uint32_t* a, const uint32_t* b) {
    asm volatile("mma.sync.aligned.m16n8k16.row.col.f32.bf16.bf16.f32 "
                 "{%0,%1,%2,%3}, {%4,%5,%6,%7}, {%8,%9}, {%0,%1,%2,%3};"
                 : "+f"(d[0]), "+f"(d[1]), "+f"(d[2]), "+f"(d[3])
                 : "r"(a[0]), "r"(a[1]), "r"(a[2]), "r"(a[3]), "r"(b[0]), "r"(b[1]));
}
__device__ __forceinline__ void bsplit(float x, __nv_bfloat16& h, __nv_bfloat16& l) {
    h = __float2bfloat16(x);
    l = __float2bfloat16(x - __bfloat162float(h));
}
__device__ __forceinline__ uint32_t bpack(__nv_bfloat16 a, __nv_bfloat16 b) {
    __nv_bfloat162 p = __halves2bfloat162(a, b);
    return *(uint32_t*)&p;
}
__device__ __forceinline__ void split4(float4 v, uint2& hh, uint2& ll) {
    __nv_bfloat16 h0, h1, h2, h3, l0, l1, l2, l3;
    bsplit(v.x, h0, l0); bsplit(v.y, h1, l1);
    bsplit(v.z, h2, l2); bsplit(v.w, h3, l3);
    hh = make_uint2(bpack(h0, h1), bpack(h2, h3));
    ll = make_uint2(bpack(l0, l1), bpack(l2, l3));
}
__device__ __forceinline__ void packhl(float a, float b, uint32_t& hh, uint32_t& ll) {
    __nv_bfloat16 ha, la, hb, lb;
    bsplit(a, ha, la); bsplit(b, hb, lb);
    hh = bpack(ha, hb); ll = bpack(la, lb);
}

// warp compute for one 64-K chunk; warp tile 64x64 (mi=4, ni=8)
// A amortized over 8 n-fragments: 85 B smem / MMA (vs 128 at 64x32)
template <bool BKN>
__device__ __forceinline__ void mma_chunk64(uint32_t ahB, uint32_t alB,
                                            uint32_t bhB, uint32_t blB,
                                            int wm, int wn, int lane,
                                            float acc[4][8][4]) {
#pragma unroll
    for (int ks = 0; ks < 4; ks++) {
        uint32_t bh[8][2], bl[8][2];
#pragma unroll
        for (int ni = 0; ni < 8; ni++) {
            uint32_t off;
            if (BKN)
                off = ((uint32_t)(ks * 16 + (lane & 7) + ((lane >> 3) & 1) * 8) * PB
                       + wn * 64 + ni * 8) * 2;
            else
                off = ((uint32_t)(wn * 64 + ni * 8 + (lane & 7)) * PA
                       + ks * 16 + ((lane >> 3) & 1) * 8) * 2;
            if (BKN) { ldmx2t(bh[ni], bhB + off); ldmx2t(bl[ni], blB + off); }
            else     { ldmx2 (bh[ni], bhB + off); ldmx2 (bl[ni], blB + off); }
        }
        uint32_t a[4][4];
        uint32_t aoff[4];
#pragma unroll
        for (int mi = 0; mi < 4; mi++) {
            aoff[mi] = ((uint32_t)(wm * 64 + mi * 16 + (lane & 15)) * PA
                        + ks * 16 + ((lane >> 4) << 3)) * 2;
            ldmx4(a[mi], ahB + aoff[mi]);
        }
#pragma unroll
        for (int mi = 0; mi < 4; mi++)
#pragma unroll
            for (int ni = 0; ni < 8; ni++) {
                mma16816(acc[mi][ni], a[mi], bh[ni]);
                mma16816(acc[mi][ni], a[mi], bl[ni]);
            }
#pragma unroll
        for (int mi = 0; mi < 4; mi++) ldmx4(a[mi], alB + aoff[mi]);
#pragma unroll
        for (int mi = 0; mi < 4; mi++)
#pragma unroll
            for (int ni = 0; ni < 8; ni++) mma16816(acc[mi][ni], a[mi], bh[ni]);
    }
}

#define GEMM_SMEM  (128 * PA * 2 * 2 + 64 * PB * 2 * 2)
#define SCORE_SMEM (128 * PA * 2 * 4)
#define ATTN2_SMEM ((2 * 64 + 4 * 128) * PQ * 2)

// ---------------- bf16x3 mma GEMM: 128 threads, 4 warps @ 64x64 ----------------
__device__ __forceinline__ void gemm_mma_body(const float* __restrict__ A,
                                              const float* __restrict__ Bm,
                                              float* __restrict__ C, int nch) {
    extern __shared__ char dsm[];
    char* Ah = dsm;
    char* Al = Ah + 128 * PA * 2;
    char* Bh = Al + 128 * PA * 2;
    char* Bl = Bh + 64 * PB * 2;
    uint32_t ahB = smem_u32(Ah), alB = smem_u32(Al);
    uint32_t bhB = smem_u32(Bh), blB = smem_u32(Bl);
    int tid = threadIdx.x;
    int wid = tid >> 5, lane = tid & 31;
    int wm = wid >> 1, wn = wid & 1;
    int crow = blockIdx.y * 128, ccol = blockIdx.x * 128;

    float acc[4][8][4];
#pragma unroll
    for (int mi = 0; mi < 4; mi++)
#pragma unroll
        for (int ni = 0; ni < 8; ni++)
#pragma unroll
            for (int e = 0; e < 4; e++) acc[mi][ni][e] = 0.f;

    for (int ch = 0; ch < nch; ch++) {
        int k0 = ch * 64;
        __syncthreads();
#pragma unroll
        for (int i = 0; i < 16; i++) {
            int idx = tid + i * 128;
            int row = idx >> 4, c4 = (idx & 15) * 4;
            float4 v = *(const float4*)&A[(size_t)(crow + row) * HID + k0 + c4];
            uint2 hh, ll;
            split4(v, hh, ll);
            *(uint2*)(Ah + ((uint32_t)row * PA + c4) * 2) = hh;
            *(uint2*)(Al + ((uint32_t)row * PA + c4) * 2) = ll;
        }
#pragma unroll
        for (int i = 0; i < 16; i++) {
            int idx = tid + i * 128;
            int kr = idx >> 5, n4 = (idx & 31) * 4;
            float4 v = *(const float4*)&Bm[(size_t)(k0 + kr) * HID + ccol + n4];
            uint2 hh, ll;
            split4(v, hh, ll);
            *(uint2*)(Bh + ((uint32_t)kr * PB + n4) * 2) = hh;
            *(uint2*)(Bl + ((uint32_t)kr * PB + n4) * 2) = ll;
        }
        __syncthreads();
        mma_chunk64<true>(ahB, alB, bhB, blB, wm, wn, lane, acc);
    }

    int quad = lane >> 2, qq = lane & 3;
#pragma unroll
    for (int mi = 0; mi < 4; mi++)
#pragma unroll
        for (int ni = 0; ni < 8; ni++) {
            int r = crow + wm * 64 + mi * 16 + quad;
            int c = ccol + wn * 64 + ni * 8 + qq * 2;
            *(float2*)&C[(size_t)r * HID + c] = make_float2(acc[mi][ni][0], acc[mi][ni][1]);
            *(float2*)&C[(size_t)(r + 8) * HID + c] = make_float2(acc[mi][ni][2], acc[mi][ni][3]);
        }
}

__global__ __launch_bounds__(128) void qkv_mma_kernel(const float* __restrict__ x,
                                                      const float* __restrict__ wq,
                                                      const float* __restrict__ wk,
                                                      const float* __restrict__ wv,
                                                      int zbase) {
    int z = zbase + blockIdx.z;
    const float* B = z == 0 ? wq : (z == 1 ? wk : wv);
    float* C = z == 0 ? g_q : (z == 1 ? g_k : g_v);
    gemm_mma_body(x, B, C, 16);
}

__global__ __launch_bounds__(128) void out_mma_kernel(const float* __restrict__ wo,
                                                      float* __restrict__ out) {
    gemm_mma_body(g_ao, wo, out, 16);
}

// ---------------- scores: bf16x3 mma Q@K^T + fused row-stat partials ----------------
__global__ __launch_bounds__(128) void scores_mma_kernel() {
    extern __shared__ char dsm[];
    char* Ah = dsm;
    char* Al = Ah + 128 * PA * 2;
    char* Bh = Al + 128 * PA * 2;
    char* Bl = Bh + 128 * PA * 2;
    uint32_t ahB = smem_u32(Ah), alB = smem_u32(Al);
    uint32_t bhB = smem_u32(Bh), blB = smem_u32(Bl);
    int tid = threadIdx.x;
    int wid = tid >> 5, lane = tid & 31;
    int wm = wid >> 1, wn = wid & 1;
    int h = blockIdx.z, q0 = blockIdx.y * 128, k0 = blockIdx.x * 128;
    const float* Aq = g_q + h * D;
    const float* Bk = g_k + h * D;

#pragma unroll
    for (int i = 0; i < 16; i++) {
        int idx = tid + i * 128;
        int row = idx >> 4, c4 = (idx & 15) * 4;
        uint32_t so = ((uint32_t)row * PA + c4) * 2;
        uint2 hh, ll;
        split4(*(const float4*)&Aq[(size_t)(q0 + row) * HID + c4], hh, ll);
        *(uint2*)(Ah + so) = hh;
        *(uint2*)(Al + so) = ll;
        split4(*(const float4*)&Bk[(size_t)(k0 + row) * HID + c4], hh, ll);
        *(uint2*)(Bh + so) = hh;
        *(uint2*)(Bl + so) = ll;
    }
    __syncthreads();

    float acc[4][8][4];
#pragma unroll
    for (int mi = 0; mi < 4; mi++)
#pragma unroll
        for (int ni = 0; ni < 8; ni++)
#pragma unroll
            for (int e = 0; e < 4; e++) acc[mi][ni][e] = 0.f;

    mma_chunk64<false>(ahB, alB, bhB, blB, wm, wn, lane, acc);

#pragma unroll
    for (int mi = 0; mi < 4; mi++)
#pragma unroll
        for (int ni = 0; ni < 8; ni++)
#pragma unroll
            for (int e = 0; e < 4; e++) acc[mi][ni][e] *= SCALE;

    float* sc = g_scores + (size_t)h * S * S;
    int quad = lane >> 2, qq = lane & 3;
#pragma unroll
    for (int mi = 0; mi < 4; mi++)
#pragma unroll
        for (int ni = 0; ni < 8; ni++) {
            int r = q0 + wm * 64 + mi * 16 + quad;
            int c = k0 + wn * 64 + ni * 8 + qq * 2;
            *(float2*)&sc[(size_t)r * S + c] = make_float2(acc[mi][ni][0], acc[mi][ni][1]);
            *(float2*)&sc[(size_t)(r + 8) * S + c] = make_float2(acc[mi][ni][2], acc[mi][ni][3]);
        }

    // per-32-col row stats: each warp owns two 32-col tiles (ni 0-3 and 4-7)
#pragma unroll
    for (int half = 0; half < 2; half++) {
        int tile = blockIdx.x * 4 + wn * 2 + half;
#pragma unroll
        for (int mi = 0; mi < 4; mi++) {
            float m0 = -1e30f, m1 = -1e30f;
#pragma unroll
            for (int nj = 0; nj < 4; nj++) {
                int ni = half * 4 + nj;
                m0 = fmaxf(m0, fmaxf(acc[mi][ni][0], acc[mi][ni][1]));
                m1 = fmaxf(m1, fmaxf(acc[mi][ni][2], acc[mi][ni][3]));
            }
            m0 = fmaxf(m0, __shfl_xor_sync(0xffffffffu, m0, 1));
            m0 = fmaxf(m0, __shfl_xor_sync(0xffffffffu, m0, 2));
            m1 = fmaxf(m1, __shfl_xor_sync(0xffffffffu, m1, 1));
            m1 = fmaxf(m1, __shfl_xor_sync(0xffffffffu, m1, 2));
            float z0 = 0.f, z1 = 0.f;
#pragma unroll
            for (int nj = 0; nj < 4; nj++) {
                int ni = half * 4 + nj;
                z0 += __expf(acc[mi][ni][0] - m0) + __expf(acc[mi][ni][1] - m0);
                z1 += __expf(acc[mi][ni][2] - m1) + __expf(acc[mi][ni][3] - m1);
            }
            z0 += __shfl_xor_sync(0xffffffffu, z0, 1);
            z0 += __shfl_xor_sync(0xffffffffu, z0, 2);
            z1 += __shfl_xor_sync(0xffffffffu, z1, 1);
            z1 += __shfl_xor_sync(0xffffffffu, z1, 2);
            if (qq == 0) {
                int r = q0 + wm * 64 + mi * 16 + quad;
                size_t p0 = (size_t)(h * S + r) * NKT + tile;
                size_t p1 = (size_t)(h * S + r + 8) * NKT + tile;
                g_pm[p0] = m0; g_pz[p0] = z0;
                g_pm[p1] = m1; g_pz[p1] = z1;
            }
        }
    }
}

// ---------------- combine partials (64 per row) ----------------
__global__ __launch_bounds__(256) void combine_kernel() {
    int row  = blockIdx.x * 8 + (threadIdx.x >> 5);
    int lane = threadIdx.x & 31;
    float pm0 = g_pm[(size_t)row * NKT + lane];
    float pz0 = g_pz[(size_t)row * NKT + lane];
    float pm1 = g_pm[(size_t)row * NKT + 32 + lane];
    float pz1 = g_pz[(size_t)row * NKT + 32 + lane];
    float m = fmaxf(pm0, pm1);
#pragma unroll
    for (int o = 16; o; o >>= 1) m = fmaxf(m, __shfl_xor_sync(0xffffffffu, m, o));
    float z = __expf(pm0 - m) * pz0 + __expf(pm1 - m) * pz1;
#pragma unroll
    for (int o = 16; o; o >>= 1) z += __shfl_xor_sync(0xffffffffu, z, o);
    if (lane == 0) {
        float rz = 1.0f / z;
        g_rowM[row] = m;
        g_rowZ[row] = rz;
        g_logZ[row] = __logf(z);
        g_maxa[row] = rz;
    }
}

// ---------------- fused entropy + influence ----------------
__global__ __launch_bounds__(256) void stats_kernel() {
    int h  = blockIdx.z;
    int q0 = blockIdx.y * 128;
    int k0 = blockIdx.x * 128;
    int tid = threadIdx.x;
    int wid = tid >> 5, lane = tid & 31;
    __shared__ float wcol[8][128];

    const float* sc = g_scores + (size_t)h * S * S;
    float c0 = 0.f, c1 = 0.f, c2 = 0.f, c3 = 0.f;

#pragma unroll 4
    for (int r = 0; r < 16; r++) {
        int row = q0 + wid * 16 + r;
        float m  = g_rowM[h * S + row];
        float rz = g_rowZ[h * S + row];
        float lz = g_logZ[h * S + row];
        float4 v = *(const float4*)&sc[(size_t)row * S + k0 + lane * 4];
        float s0 = v.x - m, s1 = v.y - m, s2 = v.z - m, s3 = v.w - m;
        float p0 = __expf(s0) * rz, p1 = __expf(s1) * rz;
        float p2 = __expf(s2) * rz, p3 = __expf(s3) * rz;
        c0 += p0; c1 += p1; c2 += p2; c3 += p3;
        float t0 = p0 * ((p0 >= 1e-8f) ? (s0 - lz) : LOG1EM8);
        float t1 = p1 * ((p1 >= 1e-8f) ? (s1 - lz) : LOG1EM8);
        float t2 = p2 * ((p2 >= 1e-8f) ? (s2 - lz) : LOG1EM8);
        float t3 = p3 * ((p3 >= 1e-8f) ? (s3 - lz) : LOG1EM8);
        float e = t0 + t1 + t2 + t3;
#pragma unroll
        for (int o = 16; o; o >>= 1) e += __shfl_xor_sync(0xffffffffu, e, o);
        if (lane == 0) atomicAdd(&g_ent[h * S + row], e);
    }
    *(float4*)&wcol[wid][lane * 4] = make_float4(c0, c1, c2, c3);
    __syncthreads();
    if (tid < 128) {
        float s = 0.f;
#pragma unroll
        for (int w = 0; w < 8; w++) s += wcol[w][tid];
        atomicAdd(&g_infl[h * S + k0 + tid], s);
    }
}

__global__ void importance_kernel() {
    int s = blockIdx.x * 256 + threadIdx.x;
    if (s >= S) return;
    float a = 0.f;
    for (int h = 0; h < H; h++)
        a += 0.4f * g_ent[h * S + s]
           + 0.3f * g_maxa[h * S + s] + 0.3f * g_infl[h * S + s];
    g_imp[s] = a * (1.0f / H);
}

__global__ void topk_kernel() {
    int i = blockIdx.x * 256 + threadIdx.x;
    if (i >= S) return;
    float vi = g_imp[i];
    int r = 0;
    for (int j = 0; j < S; j++) {
        float vj = g_imp[j];
        r += (vj > vi) || (vj == vi && j < i);
    }
    if (r < KHH) g_hhidx[r] = i;
}

// ---------------- norm-softmax-weighted 4:1 compression ----------------
__global__ __launch_bounds__(256) void compress_kernel() {
    int h = blockIdx.x;
    int which = blockIdx.y;
    const float* src = which ? g_v : g_k;
    float* dst = (which ? g_vcat : g_kcat) + ((size_t)h * KCPAD + KHH) * D;
    __shared__ float w[S];
    __shared__ float gs[LCOMP];
    __shared__ float red[256];
    int tid = threadIdx.x;

    for (int s = tid; s < S; s += 256) {
        const float* rp = src + (size_t)s * HID + h * D;
        float a = 0.f;
#pragma unroll
        for (int dd = 0; dd < 64; dd += 4) {
            float4 xv = *(const float4*)&rp[dd];
            a += xv.x * xv.x + xv.y * xv.y + xv.z * xv.z + xv.w * xv.w;
        }
        w[s] = sqrtf(a);
    }
    __syncthreads();
    float lm = -1e30f;
    for (int s = tid; s < S; s += 256) lm = fmaxf(lm, w[s]);
    red[tid] = lm; __syncthreads();
    for (int o = 128; o; o >>= 1) { if (tid < o) red[tid] = fmaxf(red[tid], red[tid + o]); __syncthreads(); }
    float m = red[0]; __syncthreads();
    float lz = 0.f;
    for (int s = tid; s < S; s += 256) { float e = __expf(w[s] - m); w[s] = e; lz += e; }
    red[tid] = lz; __syncthreads();
    for (int o = 128; o; o >>= 1) { if (tid < o) red[tid] += red[tid + o]; __syncthreads(); }
    float rz = 1.0f / red[0]; __syncthreads();
    for (int s = tid; s < S; s += 256) w[s] *= rz;
    __syncthreads();
    for (int l = tid; l < LCOMP; l += 256)
        gs[l] = w[4 * l] + w[4 * l + 1] + w[4 * l + 2] + w[4 * l + 3];
    __syncthreads();
    for (int idx = tid; idx < LCOMP * D; idx += 256) {
        int l  = idx >> 6;
        int dd = idx & 63;
        const float* rp = src + (size_t)(4 * l) * HID + h * D + dd;
        float num = w[4 * l] * rp[0] + w[4 * l + 1] * rp[HID] +
                    w[4 * l + 2] * rp[2 * HID] + w[4 * l + 3] * rp[3 * HID];
        dst[(size_t)l * D + dd] = num / (gs[l] + 1e-8f);
    }
}

__global__ void gather_kernel() {
    int idx = blockIdx.x * 256 + threadIdx.x;
    if (idx >= H * KHH * D) return;
    int d = idx & 63;
    int i = (idx >> 6) % KHH;
    int h = idx / (KHH * D);
    int s = g_hhidx[i];
    g_kcat[((size_t)h * KCPAD + i) * D + d] = g_k[(size_t)s * HID + h * D + d];
    g_vcat[((size_t)h * KCPAD + i) * D + d] = g_v[(size_t)s * HID + h * D + d];
}

// ---------------- attn2 on tensor pipe: 64 queries / block, 2 blocks/SM ----------------
__global__ __launch_bounds__(128, 2) void attn2_mma_kernel() {
    extern __shared__ char dsm[];
    char* Qh = dsm;                       // [64][PQ] bf16
    char* Ql = Qh + 64 * PQ * 2;
    char* Kh = Ql + 64 * PQ * 2;          // [128 keys][PQ d]
    char* Kl = Kh + 128 * PQ * 2;
    char* Vh = Kl + 128 * PQ * 2;
    char* Vl = Vh + 128 * PQ * 2;
    uint32_t qhB = smem_u32(Qh), qlB = smem_u32(Ql);
    uint32_t khB = smem_u32(Kh), klB = smem_u32(Kl);
    uint32_t vhB = smem_u32(Vh), vlB = smem_u32(Vl);
    int tid = threadIdx.x;
    int wid = tid >> 5, lane = tid & 31;
    int quad = lane >> 2, qq = lane & 3;
    int h = blockIdx.y, q0 = blockIdx.x * 64;

    // stage Q (hi/lo) once: 64 rows
#pragma unroll
    for (int i = 0; i < 8; i++) {
        int idx = tid + i * 128;
        int row = idx >> 4, c4 = (idx & 15) * 4;
        uint2 hh, ll;
        split4(*(const float4*)&g_q[(size_t)(q0 + row) * HID + h * D + c4], hh, ll);
        *(uint2*)(Qh + ((uint32_t)row * PQ + c4) * 2) = hh;
        *(uint2*)(Ql + ((uint32_t)row * PQ + c4) * 2) = ll;
    }
    const float* kbase = g_kcat + (size_t)h * KCPAD * D;
    const float* vbase = g_vcat + (size_t)h * KCPAD * D;

    float oacc[8][4];
#pragma unroll
    for (int ni = 0; ni < 8; ni++)
#pragma unroll
        for (int e = 0; e < 4; e++) oacc[ni][e] = 0.f;
    float m_run0 = -1e30f, m_run1 = -1e30f, z_run0 = 0.f, z_run1 = 0.f;

    for (int kt = 0; kt < KCPAD; kt += 128) {
        __syncthreads();
        // stage K,V chunk (hi/lo): 128 rows
#pragma unroll
        for (int i = 0; i < 16; i++) {
            int idx = tid + i * 128;
            int row = idx >> 4, c4 = (idx & 15) * 4;
            uint32_t so = ((uint32_t)row * PQ + c4) * 2;
            uint2 hh, ll;
            split4(*(const float4*)&kbase[(size_t)(kt + row) * D + c4], hh, ll);
            *(uint2*)(Kh + so) = hh;
            *(uint2*)(Kl + so) = ll;
            split4(*(const float4*)&vbase[(size_t)(kt + row) * D + c4], hh, ll);
            *(uint2*)(Vh + so) = hh;
            *(uint2*)(Vl + so) = ll;
        }
        __syncthreads();

        // Q frags for this warp's 16 rows
        uint32_t qfh[4][4], qfl[4][4];
#pragma unroll
        for (int ks = 0; ks < 4; ks++) {
            uint32_t aoff = ((uint32_t)(wid * 16 + (lane & 15)) * PQ
                             + ks * 16 + ((lane >> 4) << 3)) * 2;
            ldmx4(qfh[ks], qhB + aoff);
            ldmx4(qfl[ks], qlB + aoff);
        }

        // S = Q @ K^T  (16 x 128)
        float sacc[16][4];
#pragma unroll
        for (int ni = 0; ni < 16; ni++)
#pragma unroll
            for (int e = 0; e < 4; e++) sacc[ni][e] = 0.f;
#pragma unroll
        for (int ks = 0; ks < 4; ks++) {
#pragma unroll
            for (int nj = 0; nj < 8; nj++) {
                uint32_t part = lane >> 3;
                uint32_t boff = ((uint32_t)(nj * 16 + (part >> 1) * 8 + (lane & 7)) * PQ
                                 + ks * 16 + (part & 1) * 8) * 2;
                uint32_t bh[4], bl[4];
                ldmx4(bh, khB + boff);
                ldmx4(bl, klB + boff);
                mma16816(sacc[nj * 2],     qfh[ks], bh);
                mma16816(sacc[nj * 2],     qfh[ks], bl);
                mma16816(sacc[nj * 2],     qfl[ks], bh);
                mma16816(sacc[nj * 2 + 1], qfh[ks], bh + 2);
                mma16816(sacc[nj * 2 + 1], qfh[ks], bl + 2);
                mma16816(sacc[nj * 2 + 1], qfl[ks], bh + 2);
            }
        }

        // scale + mask
#pragma unroll
        for (int ni = 0; ni < 16; ni++) {
            int cg = kt + ni * 8 + qq * 2;
            bool ok0 = cg < KC, ok1 = (cg + 1) < KC;
            sacc[ni][0] = ok0 ? sacc[ni][0] * SCALE : -1e30f;
            sacc[ni][1] = ok1 ? sacc[ni][1] * SCALE : -1e30f;
            sacc[ni][2] = ok0 ? sacc[ni][2] * SCALE : -1e30f;
            sacc[ni][3] = ok1 ? sacc[ni][3] * SCALE : -1e30f;
        }
        // online softmax (rows quad, quad+8)
        float cm0 = -1e30f, cm1 = -1e30f;
#pragma unroll
        for (int ni = 0; ni < 16; ni++) {
            cm0 = fmaxf(cm0, fmaxf(sacc[ni][0], sacc[ni][1]));
            cm1 = fmaxf(cm1, fmaxf(sacc[ni][2], sacc[ni][3]));
        }
        cm0 = fmaxf(cm0, __shfl_xor_sync(0xffffffffu, cm0, 1));
        cm0 = fmaxf(cm0, __shfl_xor_sync(0xffffffffu, cm0, 2));
        cm1 = fmaxf(cm1, __shfl_xor_sync(0xffffffffu, cm1, 1));
        cm1 = fmaxf(cm1, __shfl_xor_sync(0xffffffffu, cm1, 2));
        float mn0 = fmaxf(m_run0, cm0), mn1 = fmaxf(m_run1, cm1);
        float fac0 = __expf(m_run0 - mn0), fac1 = __expf(m_run1 - mn1);
        m_run0 = mn0; m_run1 = mn1;
        float zs0 = 0.f, zs1 = 0.f;
#pragma unroll
        for (int ni = 0; ni < 16; ni++) {
            sacc[ni][0] = __expf(sacc[ni][0] - mn0);
            sacc[ni][1] = __expf(sacc[ni][1] - mn0);
            sacc[ni][2] = __expf(sacc[ni][2] - mn1);
            sacc[ni][3] = __expf(sacc[ni][3] - mn1);
            zs0 += sacc[ni][0] + sacc[ni][1];
            zs1 += sacc[ni][2] + sacc[ni][3];
        }
        zs0 += __shfl_xor_sync(0xffffffffu, zs0, 1);
        zs0 += __shfl_xor_sync(0xffffffffu, zs0, 2);
        zs1 += __shfl_xor_sync(0xffffffffu, zs1, 1);
        zs1 += __shfl_xor_sync(0xffffffffu, zs1, 2);
        z_run0 = z_run0 * fac0 + zs0;
        z_run1 = z_run1 * fac1 + zs1;
#pragma unroll
        for (int ni = 0; ni < 8; ni++) {
            oacc[ni][0] *= fac0; oacc[ni][1] *= fac0;
            oacc[ni][2] *= fac1; oacc[ni][3] *= fac1;
        }

        // P @ V : P frags from C frags in registers (hi/lo)
#pragma unroll
        for (int ks = 0; ks < 8; ks++) {
            uint32_t ph[4], pl[4];
            packhl(sacc[2 * ks][0],     sacc[2 * ks][1],     ph[0], pl[0]);
            packhl(sacc[2 * ks][2],     sacc[2 * ks][3],     ph[1], pl[1]);
            packhl(sacc[2 * ks + 1][0], sacc[2 * ks + 1][1], ph[2], pl[2]);
            packhl(sacc[2 * ks + 1][2], sacc[2 * ks + 1][3], ph[3], pl[3]);
#pragma unroll
            for (int nj = 0; nj < 4; nj++) {
                uint32_t part = lane >> 3;
                uint32_t boff = ((uint32_t)(ks * 16 + (part & 1) * 8 + (lane & 7)) * PQ
                                 + nj * 16 + (part >> 1) * 8) * 2;
                uint32_t vh[4], vl[4];
                ldmx4t(vh, vhB + boff);
                ldmx4t(vl, vlB + boff);
                mma16816(oacc[nj * 2],     ph, vh);
                mma16816(oacc[nj * 2],     ph, vl);
                mma16816(oacc[nj * 2],     pl, vh);
                mma16816(oacc[nj * 2 + 1], ph, vh + 2);
                mma16816(oacc[nj * 2 + 1], ph, vl + 2);
                mma16816(oacc[nj * 2 + 1], pl, vh + 2);
            }
        }
    }

    float rz0 = 1.0f / z_run0, rz1 = 1.0f / z_run1;
    int r0 = q0 + wid * 16 + quad;
#pragma unroll
    for (int ni = 0; ni < 8; ni++) {
        int c = h * D + ni * 8 + qq * 2;
        *(float2*)&g_ao[(size_t)r0 * HID + c] =
            make_float2(oacc[ni][0] * rz0, oacc[ni][1] * rz0);
        *(float2*)&g_ao[(size_t)(r0 + 8) * HID + c] =
            make_float2(oacc[ni][2] * rz1, oacc[ni][3] * rz1);
    }
}

// ---------------- host ----------------
extern "C" void kernel_launch(void* const* d_in, const int* in_sizes, int n_in,
                              void* d_out, int out_size) {
    const float* x  = (const float*)d_in[0];
    const float* wq = (const float*)d_in[1];
    const float* wk = (const float*)d_in[2];
    const float* wv = (const float*)d_in[3];
    const float* wo = (const float*)d_in[4];
    float* out = (float*)d_out;

    static bool init_done = false;
    static void* ent_addr = nullptr;
    static void* infl_addr = nullptr;
    static void* kcat_addr = nullptr;
    static void* vcat_addr = nullptr;
    static cudaStream_t s2;
    static cudaEvent_t evK, evB;
    if (!init_done) {
        cudaFuncSetAttribute(attn2_mma_kernel,
                             cudaFuncAttributeMaxDynamicSharedMemorySize, ATTN2_SMEM);
        cudaFuncSetAttribute(qkv_mma_kernel,
                             cudaFuncAttributeMaxDynamicSharedMemorySize, GEMM_SMEM);
        cudaFuncSetAttribute(out_mma_kernel,
                             cudaFuncAttributeMaxDynamicSharedMemorySize, GEMM_SMEM);
        cudaFuncSetAttribute(scores_mma_kernel,
                             cudaFuncAttributeMaxDynamicSharedMemorySize, SCORE_SMEM);
        cudaGetSymbolAddress(&ent_addr, g_ent);
        cudaGetSymbolAddress(&infl_addr, g_infl);
        cudaGetSymbolAddress(&kcat_addr, g_kcat);
        cudaGetSymbolAddress(&vcat_addr, g_vcat);
        cudaStreamCreateWithFlags(&s2, cudaStreamNonBlocking);
        cudaEventCreateWithFlags(&evK, cudaEventDisableTiming);
        cudaEventCreateWithFlags(&evB, cudaEventDisableTiming);
        init_done = true;
    }

    cudaMemsetAsync(ent_addr, 0, H * S * sizeof(float));
    cudaMemsetAsync(infl_addr, 0, H * S * sizeof(float));
    cudaMemsetAsync(kcat_addr, 0, (size_t)H * KCPAD * D * sizeof(float));
    cudaMemsetAsync(vcat_addr, 0, (size_t)H * KCPAD * D * sizeof(float));

    // main stream: Q,K projections
    qkv_mma_kernel<<<dim3(8, 16, 2), 128, GEMM_SMEM>>>(x, wq, wk, wv, 0);
    cudaEventRecord(evK, 0);

    // side stream: V projection + compression (overlaps DRAM-bound scores chain)
    cudaStreamWaitEvent(s2, evK, 0);
    qkv_mma_kernel<<<dim3(8, 16, 1), 128, GEMM_SMEM, s2>>>(x, wq, wk, wv, 2);
    compress_kernel<<<dim3(16, 2), 256, 0, s2>>>();
    cudaEventRecord(evB, s2);

    // main stream: heavy-hitter statistics chain (needs only Q,K)
    scores_mma_kernel<<<dim3(16, 16, 16), 128, SCORE_SMEM>>>();
    combine_kernel<<<(H * S) / 8, 256>>>();
    stats_kernel<<<dim3(16, 16, 16), 256>>>();
    importance_kernel<<<8, 256>>>();
    topk_kernel<<<8, 256>>>();

    // join: gather needs topk + V; attn2 needs kcat/vcat + Q
    cudaStreamWaitEvent(0, evB, 0);
    gather_kernel<<<(H * KHH * D + 255) / 256, 256>>>();
    attn2_mma_kernel<<<dim3(S / 64, H), 128, ATTN2_SMEM>>>();
    out_mma_kernel<<<dim3(8, 16), 128, GEMM_SMEM>>>(wo, out);
}

// round 15
// speedup vs baseline: 1.2011x; 1.0657x over previous
#include <cuda_runtime.h>
#include <cuda_bf16.h>
#include <cstdint>

#define S     2048
#define H     16
#define D     64
#define HID   1024
#define KHH   204
#define LCOMP 512
#define KC    716
#define KCPAD 768
#define SCALE 0.125f
#define NKT   64      // 32-wide k sub-tiles per score row
#define LOG1EM8 -18.420680743952367f

#define PA 72   // bf16 pitch, row-major [row][k<=64] tiles
#define PB 136  // bf16 pitch, row-major [k][n<=128] tiles
#define PQ 72   // attn2 smem pitch

// ---------------- device scratch ----------------
__device__ float g_q[S * HID];
__device__ float g_k[S * HID];
__device__ float g_v[S * HID];
__device__ float g_ao[S * HID];
__device__ float g_scores[(size_t)H * S * S];
__device__ float g_pm[(size_t)H * S * NKT];
__device__ float g_pz[(size_t)H * S * NKT];
__device__ float g_rowM[H * S];
__device__ float g_rowZ[H * S];
__device__ float g_logZ[H * S];
__device__ float g_ent[H * S];
__device__ float g_maxa[H * S];
__device__ float g_infl[H * S];
__device__ float g_imp[S];
__device__ int   g_hhidx[KHH];
// pre-split bf16 hi/lo K/V cat buffers; padding rows [KC,KCPAD) never written -> stay zero
__device__ __nv_bfloat16 g_kcath[(size_t)H * KCPAD * D];
__device__ __nv_bfloat16 g_kcatl[(size_t)H * KCPAD * D];
__device__ __nv_bfloat16 g_vcath[(size_t)H * KCPAD * D];
__device__ __nv_bfloat16 g_vcatl[(size_t)H * KCPAD * D];

// ---------------- mma.sync helpers ----------------
__device__ __forceinline__ uint32_t smem_u32(const void* p) {
    uint32_t a;
    asm("{ .reg .u64 t; cvta.to.shared.u64 t, %1; cvt.u32.u64 %0, t; }" : "=r"(a) : "l"(p));
    return a;
}
__device__ __forceinline__ void ldmx4(uint32_t* r, uint32_t addr) {
    asm volatile("ldmatrix.sync.aligned.m8n8.x4.shared.b16 {%0,%1,%2,%3}, [%4];"
                 : "=r"(r[0]), "=r"(r[1]), "=r"(r[2]), "=r"(r[3]) : "r"(addr));
}
__device__ __forceinline__ void ldmx4t(uint32_t* r, uint32_t addr) {
    asm volatile("ldmatrix.sync.aligned.m8n8.x4.trans.shared.b16 {%0,%1,%2,%3}, [%4];"
                 : "=r"(r[0]), "=r"(r[1]), "=r"(r[2]), "=r"(r[3]) : "r"(addr));
}
__device__ __forceinline__ void ldmx2(uint32_t* r, uint32_t addr) {
    asm volatile("ldmatrix.sync.aligned.m8n8.x2.shared.b16 {%0,%1}, [%2];"
                 : "=r"(r[0]), "=r"(r[1]) : "r"(addr));
}
__device__ __forceinline__ void ldmx2t(uint32_t* r, uint32_t addr) {
    asm volatile("ldmatrix.sync.aligned.m8n8.x2.trans.shared.b16 {%0,%1}, [%2];"
                 : "=r"(r[0]), "=r"(r[1]) : "r"(addr));
}
__device__ __forceinline__ void mma16816(float* d, const uint32_t* a, const uint32_t* b) {
    asm volatile("mma.sync.aligned.m16n8k16.row.col.f32.bf16.bf16.f32 "
                 "{%0,%1,%2,%3}, {%4,%5,%6,%7}, {%8,%9}, {%0,%1,%2,%3};"
                 : "+f"(d[0]), "+f"(d[1]), "+f"(d[2]), "+f"(d[3])
                 : "r"(a[0]), "r"(a[1]), "r"(a[2]), "r"(a[3]), "r"(b[0]), "r"(b[1]));
}
__device__ __forceinline__ void bsplit(float x, __nv_bfloat16& h, __nv_bfloat16& l) {
    h = __float2bfloat16(x);
    l = __float2bfloat16(x - __bfloat162float(h));
}
__device__ __forceinline__ uint32_t bpack(__nv_bfloat16 a, __nv_bfloat16 b) {
    __nv_bfloat162 p = __halves2bfloat162(a, b);
    return *(uint32_t*)&p;
}
__device__ __forceinline__ void split4(float4 v, uint2& hh, uint2& ll) {
    __nv_bfloat16 h0, h1, h2, h3, l0, l1, l2, l3;
    bsplit(v.x, h0, l0); bsplit(v.y, h1, l1);
    bsplit(v.z, h2, l2); bsplit(v.w, h3, l3);
    hh = make_uint2(bpack(h0, h1), bpack(h2, h3));
    ll = make_uint2(bpack(l0, l1), bpack(l2, l3));
}
__device__ __forceinline__ void packhl(float a, float b, uint32_t& hh, uint32_t& ll) {
    __nv_bfloat16 ha, la, hb, lb;
    bsplit(a, ha, la); bsplit(b, hb, lb);
    hh = bpack(ha, hb); ll = bpack(la, lb);
}

// warp compute for one 64-K chunk (gemm/scores kernels) — R11 version (x2 B loads)
template <bool BKN>
__device__ __forceinline__ void mma_chunk(uint32_t ahB, uint32_t alB,
                                          uint32_t bhB, uint32_t blB,
                                          int wm, int wn, int lane,
                                          float acc[4][4][4]) {
#pragma unroll
    for (int ks = 0; ks < 4; ks++) {
        uint32_t bh[4][2], bl[4][2];
#pragma unroll
        for (int ni = 0; ni < 4; ni++) {
            uint32_t off;
            if (BKN)
                off = ((uint32_t)(ks * 16 + (lane & 7) + ((lane >> 3) & 1) * 8) * PB
                       + wn * 32 + ni * 8) * 2;
            else
                off = ((uint32_t)(wn * 32 + ni * 8 + (lane & 7)) * PA
                       + ks * 16 + ((lane >> 3) & 1) * 8) * 2;
            if (BKN) { ldmx2t(bh[ni], bhB + off); ldmx2t(bl[ni], blB + off); }
            else     { ldmx2 (bh[ni], bhB + off); ldmx2 (bl[ni], blB + off); }
        }
        uint32_t a[4][4];
        uint32_t aoff[4];
#pragma unroll
        for (int mi = 0; mi < 4; mi++) {
            aoff[mi] = ((uint32_t)(wm * 64 + mi * 16 + (lane & 15)) * PA
                        + ks * 16 + ((lane >> 4) << 3)) * 2;
            ldmx4(a[mi], ahB + aoff[mi]);
        }
#pragma unroll
        for (int mi = 0; mi < 4; mi++)
#pragma unroll
            for (int ni = 0; ni < 4; ni++) {
                mma16816(acc[mi][ni], a[mi], bh[ni]);
                mma16816(acc[mi][ni], a[mi], bl[ni]);
            }
#pragma unroll
        for (int mi = 0; mi < 4; mi++) ldmx4(a[mi], alB + aoff[mi]);
#pragma unroll
        for (int mi = 0; mi < 4; mi++)
#pragma unroll
            for (int ni = 0; ni < 4; ni++) mma16816(acc[mi][ni], a[mi], bh[ni]);
    }
}

#define GEMM_SMEM  (128 * PA * 2 * 2 + 64 * PB * 2 * 2)
#define SCORE_SMEM (128 * PA * 2 * 4)
#define ATTN2_SMEM ((2 * 64 + 4 * 128) * PQ * 2)

// ---------------- bf16x3 mma GEMM (R11: 256 threads, 8 warps @ 64x32) ----------------
__device__ __forceinline__ void gemm_mma_body(const float* __restrict__ A,
                                              const float* __restrict__ Bm,
                                              float* __restrict__ C, int nch) {
    extern __shared__ char dsm[];
    char* Ah = dsm;
    char* Al = Ah + 128 * PA * 2;
    char* Bh = Al + 128 * PA * 2;
    char* Bl = Bh + 64 * PB * 2;
    uint32_t ahB = smem_u32(Ah), alB = smem_u32(Al);
    uint32_t bhB = smem_u32(Bh), blB = smem_u32(Bl);
    int tid = threadIdx.x;
    int wid = tid >> 5, lane = tid & 31;
    int wm = wid >> 2, wn = wid & 3;
    int crow = blockIdx.y * 128, ccol = blockIdx.x * 128;

    float acc[4][4][4];
#pragma unroll
    for (int mi = 0; mi < 4; mi++)
#pragma unroll
        for (int ni = 0; ni < 4; ni++)
#pragma unroll
            for (int e = 0; e < 4; e++) acc[mi][ni][e] = 0.f;

    for (int ch = 0; ch < nch; ch++) {
        int k0 = ch * 64;
        __syncthreads();
#pragma unroll
        for (int i = 0; i < 8; i++) {
            int idx = tid + i * 256;
            int row = idx >> 4, c4 = (idx & 15) * 4;
            float4 v = *(const float4*)&A[(size_t)(crow + row) * HID + k0 + c4];
            uint2 hh, ll;
            split4(v, hh, ll);
            *(uint2*)(Ah + ((uint32_t)row * PA + c4) * 2) = hh;
            *(uint2*)(Al + ((uint32_t)row * PA + c4) * 2) = ll;
        }
#pragma unroll
        for (int i = 0; i < 8; i++) {
            int idx = tid + i * 256;
            int kr = idx >> 5, n4 = (idx & 31) * 4;
            float4 v = *(const float4*)&Bm[(size_t)(k0 + kr) * HID + ccol + n4];
            uint2 hh, ll;
            split4(v, hh, ll);
            *(uint2*)(Bh + ((uint32_t)kr * PB + n4) * 2) = hh;
            *(uint2*)(Bl + ((uint32_t)kr * PB + n4) * 2) = ll;
        }
        __syncthreads();
        mma_chunk<true>(ahB, alB, bhB, blB, wm, wn, lane, acc);
    }

    int quad = lane >> 2, qq = lane & 3;
#pragma unroll
    for (int mi = 0; mi < 4; mi++)
#pragma unroll
        for (int ni = 0; ni < 4; ni++) {
            int r = crow + wm * 64 + mi * 16 + quad;
            int c = ccol + wn * 32 + ni * 8 + qq * 2;
            *(float2*)&C[(size_t)r * HID + c] = make_float2(acc[mi][ni][0], acc[mi][ni][1]);
            *(float2*)&C[(size_t)(r + 8) * HID + c] = make_float2(acc[mi][ni][2], acc[mi][ni][3]);
        }
}

__global__ __launch_bounds__(256) void qkv_mma_kernel(const float* __restrict__ x,
                                                      const float* __restrict__ wq,
                                                      const float* __restrict__ wk,
                                                      const float* __restrict__ wv,
                                                      int zbase) {
    int z = zbase + blockIdx.z;
    const float* B = z == 0 ? wq : (z == 1 ? wk : wv);
    float* C = z == 0 ? g_q : (z == 1 ? g_k : g_v);
    gemm_mma_body(x, B, C, 16);
}

__global__ __launch_bounds__(256) void out_mma_kernel(const float* __restrict__ wo,
                                                      float* __restrict__ out) {
    gemm_mma_body(g_ao, wo, out, 16);
}

// ---------------- scores: bf16x3 mma Q@K^T + fused row-stat partials (R11) ----------------
__global__ __launch_bounds__(256) void scores_mma_kernel() {
    extern __shared__ char dsm[];
    char* Ah = dsm;
    char* Al = Ah + 128 * PA * 2;
    char* Bh = Al + 128 * PA * 2;
    char* Bl = Bh + 128 * PA * 2;
    uint32_t ahB = smem_u32(Ah), alB = smem_u32(Al);
    uint32_t bhB = smem_u32(Bh), blB = smem_u32(Bl);
    int tid = threadIdx.x;
    int wid = tid >> 5, lane = tid & 31;
    int wm = wid >> 2, wn = wid & 3;
    int h = blockIdx.z, q0 = blockIdx.y * 128, k0 = blockIdx.x * 128;
    const float* Aq = g_q + h * D;
    const float* Bk = g_k + h * D;

#pragma unroll
    for (int i = 0; i < 8; i++) {
        int idx = tid + i * 256;
        int row = idx >> 4, c4 = (idx & 15) * 4;
        uint32_t so = ((uint32_t)row * PA + c4) * 2;
        uint2 hh, ll;
        split4(*(const float4*)&Aq[(size_t)(q0 + row) * HID + c4], hh, ll);
        *(uint2*)(Ah + so) = hh;
        *(uint2*)(Al + so) = ll;
        split4(*(const float4*)&Bk[(size_t)(k0 + row) * HID + c4], hh, ll);
        *(uint2*)(Bh + so) = hh;
        *(uint2*)(Bl + so) = ll;
    }
    __syncthreads();

    float acc[4][4][4];
#pragma unroll
    for (int mi = 0; mi < 4; mi++)
#pragma unroll
        for (int ni = 0; ni < 4; ni++)
#pragma unroll
            for (int e = 0; e < 4; e++) acc[mi][ni][e] = 0.f;

    mma_chunk<false>(ahB, alB, bhB, blB, wm, wn, lane, acc);

#pragma unroll
    for (int mi = 0; mi < 4; mi++)
#pragma unroll
        for (int ni = 0; ni < 4; ni++)
#pragma unroll
            for (int e = 0; e < 4; e++) acc[mi][ni][e] *= SCALE;

    float* sc = g_scores + (size_t)h * S * S;
    int quad = lane >> 2, qq = lane & 3;
#pragma unroll
    for (int mi = 0; mi < 4; mi++)
#pragma unroll
        for (int ni = 0; ni < 4; ni++) {
            int r = q0 + wm * 64 + mi * 16 + quad;
            int c = k0 + wn * 32 + ni * 8 + qq * 2;
            *(float2*)&sc[(size_t)r * S + c] = make_float2(acc[mi][ni][0], acc[mi][ni][1]);
            *(float2*)&sc[(size_t)(r + 8) * S + c] = make_float2(acc[mi][ni][2], acc[mi][ni][3]);
        }

    int tile = blockIdx.x * 4 + wn;
#pragma unroll
    for (int mi = 0; mi < 4; mi++) {
        float m0 = -1e30f, m1 = -1e30f;
#pragma unroll
        for (int ni = 0; ni < 4; ni++) {
            m0 = fmaxf(m0, fmaxf(acc[mi][ni][0], acc[mi][ni][1]));
            m1 = fmaxf(m1, fmaxf(acc[mi][ni][2], acc[mi][ni][3]));
        }
        m0 = fmaxf(m0, __shfl_xor_sync(0xffffffffu, m0, 1));
        m0 = fmaxf(m0, __shfl_xor_sync(0xffffffffu, m0, 2));
        m1 = fmaxf(m1, __shfl_xor_sync(0xffffffffu, m1, 1));
        m1 = fmaxf(m1, __shfl_xor_sync(0xffffffffu, m1, 2));
        float z0 = 0.f, z1 = 0.f;
#pragma unroll
        for (int ni = 0; ni < 4; ni++) {
            z0 += __expf(acc[mi][ni][0] - m0) + __expf(acc[mi][ni][1] - m0);
            z1 += __expf(acc[mi][ni][2] - m1) + __expf(acc[mi][ni][3] - m1);
        }
        z0 += __shfl_xor_sync(0xffffffffu, z0, 1);
        z0 += __shfl_xor_sync(0xffffffffu, z0, 2);
        z1 += __shfl_xor_sync(0xffffffffu, z1, 1);
        z1 += __shfl_xor_sync(0xffffffffu, z1, 2);
        if (qq == 0) {
            int r = q0 + wm * 64 + mi * 16 + quad;
            size_t p0 = (size_t)(h * S + r) * NKT + tile;
            size_t p1 = (size_t)(h * S + r + 8) * NKT + tile;
            g_pm[p0] = m0; g_pz[p0] = z0;
            g_pm[p1] = m1; g_pz[p1] = z1;
        }
    }
}

// ---------------- combine partials (64 per row) ----------------
__global__ __launch_bounds__(256) void combine_kernel() {
    int row  = blockIdx.x * 8 + (threadIdx.x >> 5);
    int lane = threadIdx.x & 31;
    float pm0 = g_pm[(size_t)row * NKT + lane];
    float pz0 = g_pz[(size_t)row * NKT + lane];
    float pm1 = g_pm[(size_t)row * NKT + 32 + lane];
    float pz1 = g_pz[(size_t)row * NKT + 32 + lane];
    float m = fmaxf(pm0, pm1);
#pragma unroll
    for (int o = 16; o; o >>= 1) m = fmaxf(m, __shfl_xor_sync(0xffffffffu, m, o));
    float z = __expf(pm0 - m) * pz0 + __expf(pm1 - m) * pz1;
#pragma unroll
    for (int o = 16; o; o >>= 1) z += __shfl_xor_sync(0xffffffffu, z, o);
    if (lane == 0) {
        float rz = 1.0f / z;
        g_rowM[row] = m;
        g_rowZ[row] = rz;
        g_logZ[row] = __logf(z);
        g_maxa[row] = rz;
    }
}

// ---------------- fused entropy + influence ----------------
__global__ __launch_bounds__(256) void stats_kernel() {
    int h  = blockIdx.z;
    int q0 = blockIdx.y * 128;
    int k0 = blockIdx.x * 128;
    int tid = threadIdx.x;
    int wid = tid >> 5, lane = tid & 31;
    __shared__ float wcol[8][128];

    const float* sc = g_scores + (size_t)h * S * S;
    float c0 = 0.f, c1 = 0.f, c2 = 0.f, c3 = 0.f;

#pragma unroll 4
    for (int r = 0; r < 16; r++) {
        int row = q0 + wid * 16 + r;
        float m  = g_rowM[h * S + row];
        float rz = g_rowZ[h * S + row];
        float lz = g_logZ[h * S + row];
        float4 v = *(const float4*)&sc[(size_t)row * S + k0 + lane * 4];
        float s0 = v.x - m, s1 = v.y - m, s2 = v.z - m, s3 = v.w - m;
        float p0 = __expf(s0) * rz, p1 = __expf(s1) * rz;
        float p2 = __expf(s2) * rz, p3 = __expf(s3) * rz;
        c0 += p0; c1 += p1; c2 += p2; c3 += p3;
        float t0 = p0 * ((p0 >= 1e-8f) ? (s0 - lz) : LOG1EM8);
        float t1 = p1 * ((p1 >= 1e-8f) ? (s1 - lz) : LOG1EM8);
        float t2 = p2 * ((p2 >= 1e-8f) ? (s2 - lz) : LOG1EM8);
        float t3 = p3 * ((p3 >= 1e-8f) ? (s3 - lz) : LOG1EM8);
        float e = t0 + t1 + t2 + t3;
#pragma unroll
        for (int o = 16; o; o >>= 1) e += __shfl_xor_sync(0xffffffffu, e, o);
        if (lane == 0) atomicAdd(&g_ent[h * S + row], e);
    }
    *(float4*)&wcol[wid][lane * 4] = make_float4(c0, c1, c2, c3);
    __syncthreads();
    if (tid < 128) {
        float s = 0.f;
#pragma unroll
        for (int w = 0; w < 8; w++) s += wcol[w][tid];
        atomicAdd(&g_infl[h * S + k0 + tid], s);
    }
}

__global__ void importance_kernel() {
    int s = blockIdx.x * 256 + threadIdx.x;
    if (s >= S) return;
    float a = 0.f;
    for (int h = 0; h < H; h++)
        a += 0.4f * g_ent[h * S + s]
           + 0.3f * g_maxa[h * S + s] + 0.3f * g_infl[h * S + s];
    g_imp[s] = a * (1.0f / H);
}

__global__ void topk_kernel() {
    int i = blockIdx.x * 256 + threadIdx.x;
    if (i >= S) return;
    float vi = g_imp[i];
    int r = 0;
    for (int j = 0; j < S; j++) {
        float vj = g_imp[j];
        r += (vj > vi) || (vj == vi && j < i);
    }
    if (r < KHH) g_hhidx[r] = i;
}

// ---------------- norm-softmax-weighted 4:1 compression (writes bf16 hi/lo) ----------------
__global__ __launch_bounds__(256) void compress_kernel() {
    int h = blockIdx.x;
    int which = blockIdx.y;
    const float* src = which ? g_v : g_k;
    __nv_bfloat16* dsth = (which ? g_vcath : g_kcath) + ((size_t)h * KCPAD + KHH) * D;
    __nv_bfloat16* dstl = (which ? g_vcatl : g_kcatl) + ((size_t)h * KCPAD + KHH) * D;
    __shared__ float w[S];
    __shared__ float gs[LCOMP];
    __shared__ float red[256];
    int tid = threadIdx.x;

    for (int s = tid; s < S; s += 256) {
        const float* rp = src + (size_t)s * HID + h * D;
        float a = 0.f;
#pragma unroll
        for (int dd = 0; dd < 64; dd += 4) {
            float4 xv = *(const float4*)&rp[dd];
            a += xv.x * xv.x + xv.y * xv.y + xv.z * xv.z + xv.w * xv.w;
        }
        w[s] = sqrtf(a);
    }
    __syncthreads();
    float lm = -1e30f;
    for (int s = tid; s < S; s += 256) lm = fmaxf(lm, w[s]);
    red[tid] = lm; __syncthreads();
    for (int o = 128; o; o >>= 1) { if (tid < o) red[tid] = fmaxf(red[tid], red[tid + o]); __syncthreads(); }
    float m = red[0]; __syncthreads();
    float lz = 0.f;
    for (int s = tid; s < S; s += 256) { float e = __expf(w[s] - m); w[s] = e; lz += e; }
    red[tid] = lz; __syncthreads();
    for (int o = 128; o; o >>= 1) { if (tid < o) red[tid] += red[tid + o]; __syncthreads(); }
    float rz = 1.0f / red[0]; __syncthreads();
    for (int s = tid; s < S; s += 256) w[s] *= rz;
    __syncthreads();
    for (int l = tid; l < LCOMP; l += 256)
        gs[l] = w[4 * l] + w[4 * l + 1] + w[4 * l + 2] + w[4 * l + 3];
    __syncthreads();
    for (int idx = tid; idx < LCOMP * D; idx += 256) {
        int l  = idx >> 6;
        int dd = idx & 63;
        const float* rp = src + (size_t)(4 * l) * HID + h * D + dd;
        float num = w[4 * l] * rp[0] + w[4 * l + 1] * rp[HID] +
                    w[4 * l + 2] * rp[2 * HID] + w[4 * l + 3] * rp[3 * HID];
        float val = num / (gs[l] + 1e-8f);
        __nv_bfloat16 hb, lb;
        bsplit(val, hb, lb);
        dsth[(size_t)l * D + dd] = hb;
        dstl[(size_t)l * D + dd] = lb;
    }
}

__global__ void gather_kernel() {
    int idx = blockIdx.x * 256 + threadIdx.x;
    if (idx >= H * KHH * D) return;
    int d = idx & 63;
    int i = (idx >> 6) % KHH;
    int h = idx / (KHH * D);
    int s = g_hhidx[i];
    size_t dst = ((size_t)h * KCPAD + i) * D + d;
    size_t srcp = (size_t)s * HID + h * D + d;
    __nv_bfloat16 hb, lb;
    bsplit(g_k[srcp], hb, lb);
    g_kcath[dst] = hb;
    g_kcatl[dst] = lb;
    bsplit(g_v[srcp], hb, lb);
    g_vcath[dst] = hb;
    g_vcatl[dst] = lb;
}

// ---------------- attn2 on tensor pipe: 64 queries / block, 2 blocks/SM ----------------
__global__ __launch_bounds__(128, 2) void attn2_mma_kernel() {
    extern __shared__ char dsm[];
    char* Qh = dsm;                       // [64][PQ] bf16
    char* Ql = Qh + 64 * PQ * 2;
    char* Kh = Ql + 64 * PQ * 2;          // [128 keys][PQ d]
    char* Kl = Kh + 128 * PQ * 2;
    char* Vh = Kl + 128 * PQ * 2;
    char* Vl = Vh + 128 * PQ * 2;
    uint32_t qhB = smem_u32(Qh), qlB = smem_u32(Ql);
    uint32_t khB = smem_u32(Kh), klB = smem_u32(Kl);
    uint32_t vhB = smem_u32(Vh), vlB = smem_u32(Vl);
    int tid = threadIdx.x;
    int wid = tid >> 5, lane = tid & 31;
    int quad = lane >> 2, qq = lane & 3;
    int h = blockIdx.y, q0 = blockIdx.x * 64;

    // stage Q (hi/lo) once: 64 rows
#pragma unroll
    for (int i = 0; i < 8; i++) {
        int idx = tid + i * 128;
        int row = idx >> 4, c4 = (idx & 15) * 4;
        uint2 hh, ll;
        split4(*(const float4*)&g_q[(size_t)(q0 + row) * HID + h * D + c4], hh, ll);
        *(uint2*)(Qh + ((uint32_t)row * PQ + c4) * 2) = hh;
        *(uint2*)(Ql + ((uint32_t)row * PQ + c4) * 2) = ll;
    }
    const __nv_bfloat16* kh = g_kcath + (size_t)h * KCPAD * D;
    const __nv_bfloat16* kl = g_kcatl + (size_t)h * KCPAD * D;
    const __nv_bfloat16* vh = g_vcath + (size_t)h * KCPAD * D;
    const __nv_bfloat16* vl = g_vcatl + (size_t)h * KCPAD * D;

    float oacc[8][4];
#pragma unroll
    for (int ni = 0; ni < 8; ni++)
#pragma unroll
        for (int e = 0; e < 4; e++) oacc[ni][e] = 0.f;
    float m_run0 = -1e30f, m_run1 = -1e30f, z_run0 = 0.f, z_run1 = 0.f;

    for (int kt = 0; kt < KCPAD; kt += 128) {
        __syncthreads();
        // stage K,V chunk (pre-split bf16, pure copies): 128 rows
#pragma unroll
        for (int i = 0; i < 16; i++) {
            int idx = tid + i * 128;
            int row = idx >> 4, c4 = (idx & 15) * 4;
            uint32_t so = ((uint32_t)row * PQ + c4) * 2;
            size_t go = (size_t)(kt + row) * D + c4;
            *(uint2*)(Kh + so) = *(const uint2*)&kh[go];
            *(uint2*)(Kl + so) = *(const uint2*)&kl[go];
            *(uint2*)(Vh + so) = *(const uint2*)&vh[go];
            *(uint2*)(Vl + so) = *(const uint2*)&vl[go];
        }
        __syncthreads();

        // Q frags for this warp's 16 rows
        uint32_t qfh[4][4], qfl[4][4];
#pragma unroll
        for (int ks = 0; ks < 4; ks++) {
            uint32_t aoff = ((uint32_t)(wid * 16 + (lane & 15)) * PQ
                             + ks * 16 + ((lane >> 4) << 3)) * 2;
            ldmx4(qfh[ks], qhB + aoff);
            ldmx4(qfl[ks], qlB + aoff);
        }

        // S = Q @ K^T  (16 x 128)
        float sacc[16][4];
#pragma unroll
        for (int ni = 0; ni < 16; ni++)
#pragma unroll
            for (int e = 0; e < 4; e++) sacc[ni][e] = 0.f;
#pragma unroll
        for (int ks = 0; ks < 4; ks++) {
#pragma unroll
            for (int nj = 0; nj < 8; nj++) {
                uint32_t part = lane >> 3;
                uint32_t boff = ((uint32_t)(nj * 16 + (part >> 1) * 8 + (lane & 7)) * PQ
                                 + ks * 16 + (part & 1) * 8) * 2;
                uint32_t bh[4], bl[4];
                ldmx4(bh, khB + boff);
                ldmx4(bl, klB + boff);
                mma16816(sacc[nj * 2],     qfh[ks], bh);
                mma16816(sacc[nj * 2],     qfh[ks], bl);
                mma16816(sacc[nj * 2],     qfl[ks], bh);
                mma16816(sacc[nj * 2 + 1], qfh[ks], bh + 2);
                mma16816(sacc[nj * 2 + 1], qfh[ks], bl + 2);
                mma16816(sacc[nj * 2 + 1], qfl[ks], bh + 2);
            }
        }

        // scale + mask
#pragma unroll
        for (int ni = 0; ni < 16; ni++) {
            int cg = kt + ni * 8 + qq * 2;
            bool ok0 = cg < KC, ok1 = (cg + 1) < KC;
            sacc[ni][0] = ok0 ? sacc[ni][0] * SCALE : -1e30f;
            sacc[ni][1] = ok1 ? sacc[ni][1] * SCALE : -1e30f;
            sacc[ni][2] = ok0 ? sacc[ni][2] * SCALE : -1e30f;
            sacc[ni][3] = ok1 ? sacc[ni][3] * SCALE : -1e30f;
        }
        // online softmax (rows quad, quad+8)
        float cm0 = -1e30f, cm1 = -1e30f;
#pragma unroll
        for (int ni = 0; ni < 16; ni++) {
            cm0 = fmaxf(cm0, fmaxf(sacc[ni][0], sacc[ni][1]));
            cm1 = fmaxf(cm1, fmaxf(sacc[ni][2], sacc[ni][3]));
        }
        cm0 = fmaxf(cm0, __shfl_xor_sync(0xffffffffu, cm0, 1));
        cm0 = fmaxf(cm0, __shfl_xor_sync(0xffffffffu, cm0, 2));
        cm1 = fmaxf(cm1, __shfl_xor_sync(0xffffffffu, cm1, 1));
        cm1 = fmaxf(cm1, __shfl_xor_sync(0xffffffffu, cm1, 2));
        float mn0 = fmaxf(m_run0, cm0), mn1 = fmaxf(m_run1, cm1);
        float fac0 = __expf(m_run0 - mn0), fac1 = __expf(m_run1 - mn1);
        m_run0 = mn0; m_run1 = mn1;
        float zs0 = 0.f, zs1 = 0.f;
#pragma unroll
        for (int ni = 0; ni < 16; ni++) {
            sacc[ni][0] = __expf(sacc[ni][0] - mn0);
            sacc[ni][1] = __expf(sacc[ni][1] - mn0);
            sacc[ni][2] = __expf(sacc[ni][2] - mn1);
            sacc[ni][3] = __expf(sacc[ni][3] - mn1);
            zs0 += sacc[ni][0] + sacc[ni][1];
            zs1 += sacc[ni][2] + sacc[ni][3];
        }
        zs0 += __shfl_xor_sync(0xffffffffu, zs0, 1);
        zs0 += __shfl_xor_sync(0xffffffffu, zs0, 2);
        zs1 += __shfl_xor_sync(0xffffffffu, zs1, 1);
        zs1 += __shfl_xor_sync(0xffffffffu, zs1, 2);
        z_run0 = z_run0 * fac0 + zs0;
        z_run1 = z_run1 * fac1 + zs1;
#pragma unroll
        for (int ni = 0; ni < 8; ni++) {
            oacc[ni][0] *= fac0; oacc[ni][1] *= fac0;
            oacc[ni][2] *= fac1; oacc[ni][3] *= fac1;
        }

        // P @ V : P frags from C frags in registers (hi/lo)
#pragma unroll
        for (int ks = 0; ks < 8; ks++) {
            uint32_t ph[4], pl[4];
            packhl(sacc[2 * ks][0],     sacc[2 * ks][1],     ph[0], pl[0]);
            packhl(sacc[2 * ks][2],     sacc[2 * ks][3],     ph[1], pl[1]);
            packhl(sacc[2 * ks + 1][0], sacc[2 * ks + 1][1], ph[2], pl[2]);
            packhl(sacc[2 * ks + 1][2], sacc[2 * ks + 1][3], ph[3], pl[3]);
#pragma unroll
            for (int nj = 0; nj < 4; nj++) {
                uint32_t part = lane >> 3;
                uint32_t boff = ((uint32_t)(ks * 16 + (part & 1) * 8 + (lane & 7)) * PQ
                                 + nj * 16 + (part >> 1) * 8) * 2;
                uint32_t vhf[4], vlf[4];
                ldmx4t(vhf, vhB + boff);
                ldmx4t(vlf, vlB + boff);
                mma16816(oacc[nj * 2],     ph, vhf);
                mma16816(oacc[nj * 2],     ph, vlf);
                mma16816(oacc[nj * 2],     pl, vhf);
                mma16816(oacc[nj * 2 + 1], ph, vhf + 2);
                mma16816(oacc[nj * 2 + 1], ph, vlf + 2);
                mma16816(oacc[nj * 2 + 1], pl, vhf + 2);
            }
        }
    }

    float rz0 = 1.0f / z_run0, rz1 = 1.0f / z_run1;
    int r0 = q0 + wid * 16 + quad;
#pragma unroll
    for (int ni = 0; ni < 8; ni++) {
        int c = h * D + ni * 8 + qq * 2;
        *(float2*)&g_ao[(size_t)r0 * HID + c] =
            make_float2(oacc[ni][0] * rz0, oacc[ni][1] * rz0);
        *(float2*)&g_ao[(size_t)(r0 + 8) * HID + c] =
            make_float2(oacc[ni][2] * rz1, oacc[ni][3] * rz1);
    }
}

// ---------------- host ----------------
extern "C" void kernel_launch(void* const* d_in, const int* in_sizes, int n_in,
                              void* d_out, int out_size) {
    const float* x  = (const float*)d_in[0];
    const float* wq = (const float*)d_in[1];
    const float* wk = (const float*)d_in[2];
    const float* wv = (const float*)d_in[3];
    const float* wo = (const float*)d_in[4];
    float* out = (float*)d_out;

    static bool init_done = false;
    static void* ent_addr = nullptr;
    static void* infl_addr = nullptr;
    static cudaStream_t s2;
    static cudaEvent_t evK, evB;
    if (!init_done) {
        cudaFuncSetAttribute(attn2_mma_kernel,
                             cudaFuncAttributeMaxDynamicSharedMemorySize, ATTN2_SMEM);
        cudaFuncSetAttribute(qkv_mma_kernel,
                             cudaFuncAttributeMaxDynamicSharedMemorySize, GEMM_SMEM);
        cudaFuncSetAttribute(out_mma_kernel,
                             cudaFuncAttributeMaxDynamicSharedMemorySize, GEMM_SMEM);
        cudaFuncSetAttribute(scores_mma_kernel,
                             cudaFuncAttributeMaxDynamicSharedMemorySize, SCORE_SMEM);
        cudaGetSymbolAddress(&ent_addr, g_ent);
        cudaGetSymbolAddress(&infl_addr, g_infl);
        cudaStreamCreateWithFlags(&s2, cudaStreamNonBlocking);
        cudaEventCreateWithFlags(&evK, cudaEventDisableTiming);
        cudaEventCreateWithFlags(&evB, cudaEventDisableTiming);
        init_done = true;
    }

    cudaMemsetAsync(ent_addr, 0, H * S * sizeof(float));
    cudaMemsetAsync(infl_addr, 0, H * S * sizeof(float));

    // main stream: Q,K projections
    qkv_mma_kernel<<<dim3(8, 16, 2), 256, GEMM_SMEM>>>(x, wq, wk, wv, 0);
    cudaEventRecord(evK, 0);

    // side stream: V projection + compression (overlaps DRAM-bound scores chain)
    cudaStreamWaitEvent(s2, evK, 0);
    qkv_mma_kernel<<<dim3(8, 16, 1), 256, GEMM_SMEM, s2>>>(x, wq, wk, wv, 2);
    compress_kernel<<<dim3(16, 2), 256, 0, s2>>>();
    cudaEventRecord(evB, s2);

    // main stream: heavy-hitter statistics chain (needs only Q,K)
    scores_mma_kernel<<<dim3(16, 16, 16), 256, SCORE_SMEM>>>();
    combine_kernel<<<(H * S) / 8, 256>>>();
    stats_kernel<<<dim3(16, 16, 16), 256>>>();
    importance_kernel<<<8, 256>>>();
    topk_kernel<<<8, 256>>>();

    // join: gather needs topk + K,V; attn2 needs kcat/vcat + Q
    cudaStreamWaitEvent(0, evB, 0);
    gather_kernel<<<(H * KHH * D + 255) / 256, 256>>>();
    attn2_mma_kernel<<<dim3(S / 64, H), 128, ATTN2_SMEM>>>();
    out_mma_kernel<<<dim3(8, 16), 256, GEMM_SMEM>>>(wo, out);
}

// round 16
// speedup vs baseline: 1.2243x; 1.0193x over previous
#include <cuda_runtime.h>
#include <cuda_bf16.h>
#include <cstdint>

#define S     2048
#define H     16
#define D     64
#define HID   1024
#define KHH   204
#define LCOMP 512
#define KC    716
#define KCPAD 768
#define SCALE 0.125f
#define NKT   64      // 32-wide k sub-tiles per score row
#define LOG1EM8 -18.420680743952367f

#define PA 72   // bf16 pitch, row-major [row][k<=64] tiles
#define PB 136  // bf16 pitch, row-major [k][n<=128] tiles
#define PQ 72   // attn2 smem pitch

// ---------------- device scratch ----------------
__device__ float g_q[S * HID];
__device__ float g_k[S * HID];
__device__ float g_v[S * HID];
__device__ float g_ao[S * HID];
__device__ float g_scores[(size_t)H * S * S];
__device__ float g_pm[(size_t)H * S * NKT];
__device__ float g_pz[(size_t)H * S * NKT];
__device__ float g_rowM[H * S];
__device__ float g_rowZ[H * S];
__device__ float g_logZ[H * S];
__device__ float g_ent[H * S];
__device__ float g_maxa[H * S];
__device__ float g_infl[H * S];
__device__ float g_imp[S];
__device__ int   g_hhidx[KHH];
// pre-split bf16 hi/lo K/V cat buffers; padding rows [KC,KCPAD) never written -> stay zero
__device__ __nv_bfloat16 g_kcath[(size_t)H * KCPAD * D];
__device__ __nv_bfloat16 g_kcatl[(size_t)H * KCPAD * D];
__device__ __nv_bfloat16 g_vcath[(size_t)H * KCPAD * D];
__device__ __nv_bfloat16 g_vcatl[(size_t)H * KCPAD * D];

// ---------------- mma.sync helpers ----------------
__device__ __forceinline__ uint32_t smem_u32(const void* p) {
    uint32_t a;
    asm("{ .reg .u64 t; cvta.to.shared.u64 t, %1; cvt.u32.u64 %0, t; }" : "=r"(a) : "l"(p));
    return a;
}
__device__ __forceinline__ void ldmx4(uint32_t* r, uint32_t addr) {
    asm volatile("ldmatrix.sync.aligned.m8n8.x4.shared.b16 {%0,%1,%2,%3}, [%4];"
                 : "=r"(r[0]), "=r"(r[1]), "=r"(r[2]), "=r"(r[3]) : "r"(addr));
}
__device__ __forceinline__ void ldmx4t(uint32_t* r, uint32_t addr) {
    asm volatile("ldmatrix.sync.aligned.m8n8.x4.trans.shared.b16 {%0,%1,%2,%3}, [%4];"
                 : "=r"(r[0]), "=r"(r[1]), "=r"(r[2]), "=r"(r[3]) : "r"(addr));
}
__device__ __forceinline__ void ldmx2(uint32_t* r, uint32_t addr) {
    asm volatile("ldmatrix.sync.aligned.m8n8.x2.shared.b16 {%0,%1}, [%2];"
                 : "=r"(r[0]), "=r"(r[1]) : "r"(addr));
}
__device__ __forceinline__ void ldmx2t(uint32_t* r, uint32_t addr) {
    asm volatile("ldmatrix.sync.aligned.m8n8.x2.trans.shared.b16 {%0,%1}, [%2];"
                 : "=r"(r[0]), "=r"(r[1]) : "r"(addr));
}
__device__ __forceinline__ void mma16816(float* d, const uint32_t* a, const uint32_t* b) {
    asm volatile("mma.sync.aligned.m16n8k16.row.col.f32.bf16.bf16.f32 "
                 "{%0,%1,%2,%3}, {%4,%5,%6,%7}, {%8,%9}, {%0,%1,%2,%3};"
                 : "+f"(d[0]), "+f"(d[1]), "+f"(d[2]), "+f"(d[3])
                 : "r"(a[0]), "r"(a[1]), "r"(a[2]), "r"(a[3]), "r"(b[0]), "r"(b[1]));
}
__device__ __forceinline__ void bsplit(float x, __nv_bfloat16& h, __nv_bfloat16& l) {
    h = __float2bfloat16(x);
    l = __float2bfloat16(x - __bfloat162float(h));
}
__device__ __forceinline__ uint32_t bpack(__nv_bfloat16 a, __nv_bfloat16 b) {
    __nv_bfloat162 p = __halves2bfloat162(a, b);
    return *(uint32_t*)&p;
}
__device__ __forceinline__ void split4(float4 v, uint2& hh, uint2& ll) {
    __nv_bfloat16 h0, h1, h2, h3, l0, l1, l2, l3;
    bsplit(v.x, h0, l0); bsplit(v.y, h1, l1);
    bsplit(v.z, h2, l2); bsplit(v.w, h3, l3);
    hh = make_uint2(bpack(h0, h1), bpack(h2, h3));
    ll = make_uint2(bpack(l0, l1), bpack(l2, l3));
}
__device__ __forceinline__ void packhl(float a, float b, uint32_t& hh, uint32_t& ll) {
    __nv_bfloat16 ha, la, hb, lb;
    bsplit(a, ha, la); bsplit(b, hb, lb);
    hh = bpack(ha, hb); ll = bpack(la, lb);
}

// warp compute for one 64-K chunk (gemm/scores kernels)
template <bool BKN>
__device__ __forceinline__ void mma_chunk(uint32_t ahB, uint32_t alB,
                                          uint32_t bhB, uint32_t blB,
                                          int wm, int wn, int lane,
                                          float acc[4][4][4]) {
#pragma unroll
    for (int ks = 0; ks < 4; ks++) {
        uint32_t bh[4][2], bl[4][2];
#pragma unroll
        for (int ni = 0; ni < 4; ni++) {
            uint32_t off;
            if (BKN)
                off = ((uint32_t)(ks * 16 + (lane & 7) + ((lane >> 3) & 1) * 8) * PB
                       + wn * 32 + ni * 8) * 2;
            else
                off = ((uint32_t)(wn * 32 + ni * 8 + (lane & 7)) * PA
                       + ks * 16 + ((lane >> 3) & 1) * 8) * 2;
            if (BKN) { ldmx2t(bh[ni], bhB + off); ldmx2t(bl[ni], blB + off); }
            else     { ldmx2 (bh[ni], bhB + off); ldmx2 (bl[ni], blB + off); }
        }
        uint32_t a[4][4];
        uint32_t aoff[4];
#pragma unroll
        for (int mi = 0; mi < 4; mi++) {
            aoff[mi] = ((uint32_t)(wm * 64 + mi * 16 + (lane & 15)) * PA
                        + ks * 16 + ((lane >> 4) << 3)) * 2;
            ldmx4(a[mi], ahB + aoff[mi]);
        }
#pragma unroll
        for (int mi = 0; mi < 4; mi++)
#pragma unroll
            for (int ni = 0; ni < 4; ni++) {
                mma16816(acc[mi][ni], a[mi], bh[ni]);
                mma16816(acc[mi][ni], a[mi], bl[ni]);
            }
#pragma unroll
        for (int mi = 0; mi < 4; mi++) ldmx4(a[mi], alB + aoff[mi]);
#pragma unroll
        for (int mi = 0; mi < 4; mi++)
#pragma unroll
            for (int ni = 0; ni < 4; ni++) mma16816(acc[mi][ni], a[mi], bh[ni]);
    }
}

#define GEMM_SMEM  (128 * PA * 2 * 2 + 64 * PB * 2 * 2)
#define SCORE_SMEM (128 * PA * 2 * 4)
#define ATTN2_SMEM ((2 * 64 + 4 * 128) * PQ * 2)

// ---------------- bf16x3 mma GEMM (256 threads, 8 warps @ 64x32) ----------------
__device__ __forceinline__ void gemm_mma_body(const float* __restrict__ A,
                                              const float* __restrict__ Bm,
                                              float* __restrict__ C, int nch) {
    extern __shared__ char dsm[];
    char* Ah = dsm;
    char* Al = Ah + 128 * PA * 2;
    char* Bh = Al + 128 * PA * 2;
    char* Bl = Bh + 64 * PB * 2;
    uint32_t ahB = smem_u32(Ah), alB = smem_u32(Al);
    uint32_t bhB = smem_u32(Bh), blB = smem_u32(Bl);
    int tid = threadIdx.x;
    int wid = tid >> 5, lane = tid & 31;
    int wm = wid >> 2, wn = wid & 3;
    int crow = blockIdx.y * 128, ccol = blockIdx.x * 128;

    float acc[4][4][4];
#pragma unroll
    for (int mi = 0; mi < 4; mi++)
#pragma unroll
        for (int ni = 0; ni < 4; ni++)
#pragma unroll
            for (int e = 0; e < 4; e++) acc[mi][ni][e] = 0.f;

    for (int ch = 0; ch < nch; ch++) {
        int k0 = ch * 64;
        __syncthreads();
#pragma unroll
        for (int i = 0; i < 8; i++) {
            int idx = tid + i * 256;
            int row = idx >> 4, c4 = (idx & 15) * 4;
            float4 v = *(const float4*)&A[(size_t)(crow + row) * HID + k0 + c4];
            uint2 hh, ll;
            split4(v, hh, ll);
            *(uint2*)(Ah + ((uint32_t)row * PA + c4) * 2) = hh;
            *(uint2*)(Al + ((uint32_t)row * PA + c4) * 2) = ll;
        }
#pragma unroll
        for (int i = 0; i < 8; i++) {
            int idx = tid + i * 256;
            int kr = idx >> 5, n4 = (idx & 31) * 4;
            float4 v = *(const float4*)&Bm[(size_t)(k0 + kr) * HID + ccol + n4];
            uint2 hh, ll;
            split4(v, hh, ll);
            *(uint2*)(Bh + ((uint32_t)kr * PB + n4) * 2) = hh;
            *(uint2*)(Bl + ((uint32_t)kr * PB + n4) * 2) = ll;
        }
        __syncthreads();
        mma_chunk<true>(ahB, alB, bhB, blB, wm, wn, lane, acc);
    }

    int quad = lane >> 2, qq = lane & 3;
#pragma unroll
    for (int mi = 0; mi < 4; mi++)
#pragma unroll
        for (int ni = 0; ni < 4; ni++) {
            int r = crow + wm * 64 + mi * 16 + quad;
            int c = ccol + wn * 32 + ni * 8 + qq * 2;
            *(float2*)&C[(size_t)r * HID + c] = make_float2(acc[mi][ni][0], acc[mi][ni][1]);
            *(float2*)&C[(size_t)(r + 8) * HID + c] = make_float2(acc[mi][ni][2], acc[mi][ni][3]);
        }
}

__global__ __launch_bounds__(256) void qkv_mma_kernel(const float* __restrict__ x,
                                                      const float* __restrict__ wq,
                                                      const float* __restrict__ wk,
                                                      const float* __restrict__ wv,
                                                      int zbase) {
    int z = zbase + blockIdx.z;
    const float* B = z == 0 ? wq : (z == 1 ? wk : wv);
    float* C = z == 0 ? g_q : (z == 1 ? g_k : g_v);
    gemm_mma_body(x, B, C, 16);
}

__global__ __launch_bounds__(256) void out_mma_kernel(const float* __restrict__ wo,
                                                      float* __restrict__ out) {
    gemm_mma_body(g_ao, wo, out, 16);
}

// ---------------- scores: bf16x3 mma Q@K^T + fused row-stat partials ----------------
__global__ __launch_bounds__(256) void scores_mma_kernel(int hbase) {
    extern __shared__ char dsm[];
    char* Ah = dsm;
    char* Al = Ah + 128 * PA * 2;
    char* Bh = Al + 128 * PA * 2;
    char* Bl = Bh + 128 * PA * 2;
    uint32_t ahB = smem_u32(Ah), alB = smem_u32(Al);
    uint32_t bhB = smem_u32(Bh), blB = smem_u32(Bl);
    int tid = threadIdx.x;
    int wid = tid >> 5, lane = tid & 31;
    int wm = wid >> 2, wn = wid & 3;
    int h = hbase + blockIdx.z, q0 = blockIdx.y * 128, k0 = blockIdx.x * 128;
    const float* Aq = g_q + h * D;
    const float* Bk = g_k + h * D;

#pragma unroll
    for (int i = 0; i < 8; i++) {
        int idx = tid + i * 256;
        int row = idx >> 4, c4 = (idx & 15) * 4;
        uint32_t so = ((uint32_t)row * PA + c4) * 2;
        uint2 hh, ll;
        split4(*(const float4*)&Aq[(size_t)(q0 + row) * HID + c4], hh, ll);
        *(uint2*)(Ah + so) = hh;
        *(uint2*)(Al + so) = ll;
        split4(*(const float4*)&Bk[(size_t)(k0 + row) * HID + c4], hh, ll);
        *(uint2*)(Bh + so) = hh;
        *(uint2*)(Bl + so) = ll;
    }
    __syncthreads();

    float acc[4][4][4];
#pragma unroll
    for (int mi = 0; mi < 4; mi++)
#pragma unroll
        for (int ni = 0; ni < 4; ni++)
#pragma unroll
            for (int e = 0; e < 4; e++) acc[mi][ni][e] = 0.f;

    mma_chunk<false>(ahB, alB, bhB, blB, wm, wn, lane, acc);

#pragma unroll
    for (int mi = 0; mi < 4; mi++)
#pragma unroll
        for (int ni = 0; ni < 4; ni++)
#pragma unroll
            for (int e = 0; e < 4; e++) acc[mi][ni][e] *= SCALE;

    float* sc = g_scores + (size_t)h * S * S;
    int quad = lane >> 2, qq = lane & 3;
#pragma unroll
    for (int mi = 0; mi < 4; mi++)
#pragma unroll
        for (int ni = 0; ni < 4; ni++) {
            int r = q0 + wm * 64 + mi * 16 + quad;
            int c = k0 + wn * 32 + ni * 8 + qq * 2;
            *(float2*)&sc[(size_t)r * S + c] = make_float2(acc[mi][ni][0], acc[mi][ni][1]);
            *(float2*)&sc[(size_t)(r + 8) * S + c] = make_float2(acc[mi][ni][2], acc[mi][ni][3]);
        }

    int tile = blockIdx.x * 4 + wn;
#pragma unroll
    for (int mi = 0; mi < 4; mi++) {
        float m0 = -1e30f, m1 = -1e30f;
#pragma unroll
        for (int ni = 0; ni < 4; ni++) {
            m0 = fmaxf(m0, fmaxf(acc[mi][ni][0], acc[mi][ni][1]));
            m1 = fmaxf(m1, fmaxf(acc[mi][ni][2], acc[mi][ni][3]));
        }
        m0 = fmaxf(m0, __shfl_xor_sync(0xffffffffu, m0, 1));
        m0 = fmaxf(m0, __shfl_xor_sync(0xffffffffu, m0, 2));
        m1 = fmaxf(m1, __shfl_xor_sync(0xffffffffu, m1, 1));
        m1 = fmaxf(m1, __shfl_xor_sync(0xffffffffu, m1, 2));
        float z0 = 0.f, z1 = 0.f;
#pragma unroll
        for (int ni = 0; ni < 4; ni++) {
            z0 += __expf(acc[mi][ni][0] - m0) + __expf(acc[mi][ni][1] - m0);
            z1 += __expf(acc[mi][ni][2] - m1) + __expf(acc[mi][ni][3] - m1);
        }
        z0 += __shfl_xor_sync(0xffffffffu, z0, 1);
        z0 += __shfl_xor_sync(0xffffffffu, z0, 2);
        z1 += __shfl_xor_sync(0xffffffffu, z1, 1);
        z1 += __shfl_xor_sync(0xffffffffu, z1, 2);
        if (qq == 0) {
            int r = q0 + wm * 64 + mi * 16 + quad;
            size_t p0 = (size_t)(h * S + r) * NKT + tile;
            size_t p1 = (size_t)(h * S + r + 8) * NKT + tile;
            g_pm[p0] = m0; g_pz[p0] = z0;
            g_pm[p1] = m1; g_pz[p1] = z1;
        }
    }
}

// ---------------- combine partials (64 per row) ----------------
__global__ __launch_bounds__(256) void combine_kernel(int rowbase) {
    int row  = rowbase + blockIdx.x * 8 + (threadIdx.x >> 5);
    int lane = threadIdx.x & 31;
    float pm0 = g_pm[(size_t)row * NKT + lane];
    float pz0 = g_pz[(size_t)row * NKT + lane];
    float pm1 = g_pm[(size_t)row * NKT + 32 + lane];
    float pz1 = g_pz[(size_t)row * NKT + 32 + lane];
    float m = fmaxf(pm0, pm1);
#pragma unroll
    for (int o = 16; o; o >>= 1) m = fmaxf(m, __shfl_xor_sync(0xffffffffu, m, o));
    float z = __expf(pm0 - m) * pz0 + __expf(pm1 - m) * pz1;
#pragma unroll
    for (int o = 16; o; o >>= 1) z += __shfl_xor_sync(0xffffffffu, z, o);
    if (lane == 0) {
        float rz = 1.0f / z;
        g_rowM[row] = m;
        g_rowZ[row] = rz;
        g_logZ[row] = __logf(z);
        g_maxa[row] = rz;
    }
}

// ---------------- fused entropy + influence ----------------
__global__ __launch_bounds__(256) void stats_kernel(int hbase) {
    int h  = hbase + blockIdx.z;
    int q0 = blockIdx.y * 128;
    int k0 = blockIdx.x * 128;
    int tid = threadIdx.x;
    int wid = tid >> 5, lane = tid & 31;
    __shared__ float wcol[8][128];

    const float* sc = g_scores + (size_t)h * S * S;
    float c0 = 0.f, c1 = 0.f, c2 = 0.f, c3 = 0.f;

#pragma unroll 4
    for (int r = 0; r < 16; r++) {
        int row = q0 + wid * 16 + r;
        float m  = g_rowM[h * S + row];
        float rz = g_rowZ[h * S + row];
        float lz = g_logZ[h * S + row];
        float4 v = *(const float4*)&sc[(size_t)row * S + k0 + lane * 4];
        float s0 = v.x - m, s1 = v.y - m, s2 = v.z - m, s3 = v.w - m;
        float p0 = __expf(s0) * rz, p1 = __expf(s1) * rz;
        float p2 = __expf(s2) * rz, p3 = __expf(s3) * rz;
        c0 += p0; c1 += p1; c2 += p2; c3 += p3;
        float t0 = p0 * ((p0 >= 1e-8f) ? (s0 - lz) : LOG1EM8);
        float t1 = p1 * ((p1 >= 1e-8f) ? (s1 - lz) : LOG1EM8);
        float t2 = p2 * ((p2 >= 1e-8f) ? (s2 - lz) : LOG1EM8);
        float t3 = p3 * ((p3 >= 1e-8f) ? (s3 - lz) : LOG1EM8);
        float e = t0 + t1 + t2 + t3;
#pragma unroll
        for (int o = 16; o; o >>= 1) e += __shfl_xor_sync(0xffffffffu, e, o);
        if (lane == 0) atomicAdd(&g_ent[h * S + row], e);
    }
    *(float4*)&wcol[wid][lane * 4] = make_float4(c0, c1, c2, c3);
    __syncthreads();
    if (tid < 128) {
        float s = 0.f;
#pragma unroll
        for (int w = 0; w < 8; w++) s += wcol[w][tid];
        atomicAdd(&g_infl[h * S + k0 + tid], s);
    }
}

__global__ void importance_kernel() {
    int s = blockIdx.x * 256 + threadIdx.x;
    if (s >= S) return;
    float a = 0.f;
    for (int h = 0; h < H; h++)
        a += 0.4f * g_ent[h * S + s]
           + 0.3f * g_maxa[h * S + s] + 0.3f * g_infl[h * S + s];
    g_imp[s] = a * (1.0f / H);
}

__global__ void topk_kernel() {
    int i = blockIdx.x * 256 + threadIdx.x;
    if (i >= S) return;
    float vi = g_imp[i];
    int r = 0;
    for (int j = 0; j < S; j++) {
        float vj = g_imp[j];
        r += (vj > vi) || (vj == vi && j < i);
    }
    if (r < KHH) g_hhidx[r] = i;
}

// ---------------- norm-softmax-weighted 4:1 compression (writes bf16 hi/lo) ----------------
__global__ __launch_bounds__(256) void compress_kernel() {
    int h = blockIdx.x;
    int which = blockIdx.y;
    const float* src = which ? g_v : g_k;
    __nv_bfloat16* dsth = (which ? g_vcath : g_kcath) + ((size_t)h * KCPAD + KHH) * D;
    __nv_bfloat16* dstl = (which ? g_vcatl : g_kcatl) + ((size_t)h * KCPAD + KHH) * D;
    __shared__ float w[S];
    __shared__ float gs[LCOMP];
    __shared__ float red[256];
    int tid = threadIdx.x;

    for (int s = tid; s < S; s += 256) {
        const float* rp = src + (size_t)s * HID + h * D;
        float a = 0.f;
#pragma unroll
        for (int dd = 0; dd < 64; dd += 4) {
            float4 xv = *(const float4*)&rp[dd];
            a += xv.x * xv.x + xv.y * xv.y + xv.z * xv.z + xv.w * xv.w;
        }
        w[s] = sqrtf(a);
    }
    __syncthreads();
    float lm = -1e30f;
    for (int s = tid; s < S; s += 256) lm = fmaxf(lm, w[s]);
    red[tid] = lm; __syncthreads();
    for (int o = 128; o; o >>= 1) { if (tid < o) red[tid] = fmaxf(red[tid], red[tid + o]); __syncthreads(); }
    float m = red[0]; __syncthreads();
    float lz = 0.f;
    for (int s = tid; s < S; s += 256) { float e = __expf(w[s] - m); w[s] = e; lz += e; }
    red[tid] = lz; __syncthreads();
    for (int o = 128; o; o >>= 1) { if (tid < o) red[tid] += red[tid + o]; __syncthreads(); }
    float rz = 1.0f / red[0]; __syncthreads();
    for (int s = tid; s < S; s += 256) w[s] *= rz;
    __syncthreads();
    for (int l = tid; l < LCOMP; l += 256)
        gs[l] = w[4 * l] + w[4 * l + 1] + w[4 * l + 2] + w[4 * l + 3];
    __syncthreads();
    for (int idx = tid; idx < LCOMP * D; idx += 256) {
        int l  = idx >> 6;
        int dd = idx & 63;
        const float* rp = src + (size_t)(4 * l) * HID + h * D + dd;
        float num = w[4 * l] * rp[0] + w[4 * l + 1] * rp[HID] +
                    w[4 * l + 2] * rp[2 * HID] + w[4 * l + 3] * rp[3 * HID];
        float val = num / (gs[l] + 1e-8f);
        __nv_bfloat16 hb, lb;
        bsplit(val, hb, lb);
        dsth[(size_t)l * D + dd] = hb;
        dstl[(size_t)l * D + dd] = lb;
    }
}

__global__ void gather_kernel() {
    int idx = blockIdx.x * 256 + threadIdx.x;
    if (idx >= H * KHH * D) return;
    int d = idx & 63;
    int i = (idx >> 6) % KHH;
    int h = idx / (KHH * D);
    int s = g_hhidx[i];
    size_t dst = ((size_t)h * KCPAD + i) * D + d;
    size_t srcp = (size_t)s * HID + h * D + d;
    __nv_bfloat16 hb, lb;
    bsplit(g_k[srcp], hb, lb);
    g_kcath[dst] = hb;
    g_kcatl[dst] = lb;
    bsplit(g_v[srcp], hb, lb);
    g_vcath[dst] = hb;
    g_vcatl[dst] = lb;
}

// ---------------- attn2 on tensor pipe: 64 queries / block, 2 blocks/SM ----------------
__global__ __launch_bounds__(128, 2) void attn2_mma_kernel() {
    extern __shared__ char dsm[];
    char* Qh = dsm;                       // [64][PQ] bf16
    char* Ql = Qh + 64 * PQ * 2;
    char* Kh = Ql + 64 * PQ * 2;          // [128 keys][PQ d]
    char* Kl = Kh + 128 * PQ * 2;
    char* Vh = Kl + 128 * PQ * 2;
    char* Vl = Vh + 128 * PQ * 2;
    uint32_t qhB = smem_u32(Qh), qlB = smem_u32(Ql);
    uint32_t khB = smem_u32(Kh), klB = smem_u32(Kl);
    uint32_t vhB = smem_u32(Vh), vlB = smem_u32(Vl);
    int tid = threadIdx.x;
    int wid = tid >> 5, lane = tid & 31;
    int quad = lane >> 2, qq = lane & 3;
    int h = blockIdx.y, q0 = blockIdx.x * 64;

#pragma unroll
    for (int i = 0; i < 8; i++) {
        int idx = tid + i * 128;
        int row = idx >> 4, c4 = (idx & 15) * 4;
        uint2 hh, ll;
        split4(*(const float4*)&g_q[(size_t)(q0 + row) * HID + h * D + c4], hh, ll);
        *(uint2*)(Qh + ((uint32_t)row * PQ + c4) * 2) = hh;
        *(uint2*)(Ql + ((uint32_t)row * PQ + c4) * 2) = ll;
    }
    const __nv_bfloat16* kh = g_kcath + (size_t)h * KCPAD * D;
    const __nv_bfloat16* kl = g_kcatl + (size_t)h * KCPAD * D;
    const __nv_bfloat16* vh = g_vcath + (size_t)h * KCPAD * D;
    const __nv_bfloat16* vl = g_vcatl + (size_t)h * KCPAD * D;

    float oacc[8][4];
#pragma unroll
    for (int ni = 0; ni < 8; ni++)
#pragma unroll
        for (int e = 0; e < 4; e++) oacc[ni][e] = 0.f;
    float m_run0 = -1e30f, m_run1 = -1e30f, z_run0 = 0.f, z_run1 = 0.f;

    for (int kt = 0; kt < KCPAD; kt += 128) {
        __syncthreads();
#pragma unroll
        for (int i = 0; i < 16; i++) {
            int idx = tid + i * 128;
            int row = idx >> 4, c4 = (idx & 15) * 4;
            uint32_t so = ((uint32_t)row * PQ + c4) * 2;
            size_t go = (size_t)(kt + row) * D + c4;
            *(uint2*)(Kh + so) = *(const uint2*)&kh[go];
            *(uint2*)(Kl + so) = *(const uint2*)&kl[go];
            *(uint2*)(Vh + so) = *(const uint2*)&vh[go];
            *(uint2*)(Vl + so) = *(const uint2*)&vl[go];
        }
        __syncthreads();

        uint32_t qfh[4][4], qfl[4][4];
#pragma unroll
        for (int ks = 0; ks < 4; ks++) {
            uint32_t aoff = ((uint32_t)(wid * 16 + (lane & 15)) * PQ
                             + ks * 16 + ((lane >> 4) << 3)) * 2;
            ldmx4(qfh[ks], qhB + aoff);
            ldmx4(qfl[ks], qlB + aoff);
        }

        float sacc[16][4];
#pragma unroll
        for (int ni = 0; ni < 16; ni++)
#pragma unroll
            for (int e = 0; e < 4; e++) sacc[ni][e] = 0.f;
#pragma unroll
        for (int ks = 0; ks < 4; ks++) {
#pragma unroll
            for (int nj = 0; nj < 8; nj++) {
                uint32_t part = lane >> 3;
                uint32_t boff = ((uint32_t)(nj * 16 + (part >> 1) * 8 + (lane & 7)) * PQ
                                 + ks * 16 + (part & 1) * 8) * 2;
                uint32_t bh[4], bl[4];
                ldmx4(bh, khB + boff);
                ldmx4(bl, klB + boff);
                mma16816(sacc[nj * 2],     qfh[ks], bh);
                mma16816(sacc[nj * 2],     qfh[ks], bl);
                mma16816(sacc[nj * 2],     qfl[ks], bh);
                mma16816(sacc[nj * 2 + 1], qfh[ks], bh + 2);
                mma16816(sacc[nj * 2 + 1], qfh[ks], bl + 2);
                mma16816(sacc[nj * 2 + 1], qfl[ks], bh + 2);
            }
        }

#pragma unroll
        for (int ni = 0; ni < 16; ni++) {
            int cg = kt + ni * 8 + qq * 2;
            bool ok0 = cg < KC, ok1 = (cg + 1) < KC;
            sacc[ni][0] = ok0 ? sacc[ni][0] * SCALE : -1e30f;
            sacc[ni][1] = ok1 ? sacc[ni][1] * SCALE : -1e30f;
            sacc[ni][2] = ok0 ? sacc[ni][2] * SCALE : -1e30f;
            sacc[ni][3] = ok1 ? sacc[ni][3] * SCALE : -1e30f;
        }
        float cm0 = -1e30f, cm1 = -1e30f;
#pragma unroll
        for (int ni = 0; ni < 16; ni++) {
            cm0 = fmaxf(cm0, fmaxf(sacc[ni][0], sacc[ni][1]));
            cm1 = fmaxf(cm1, fmaxf(sacc[ni][2], sacc[ni][3]));
        }
        cm0 = fmaxf(cm0, __shfl_xor_sync(0xffffffffu, cm0, 1));
        cm0 = fmaxf(cm0, __shfl_xor_sync(0xffffffffu, cm0, 2));
        cm1 = fmaxf(cm1, __shfl_xor_sync(0xffffffffu, cm1, 1));
        cm1 = fmaxf(cm1, __shfl_xor_sync(0xffffffffu, cm1, 2));
        float mn0 = fmaxf(m_run0, cm0), mn1 = fmaxf(m_run1, cm1);
        float fac0 = __expf(m_run0 - mn0), fac1 = __expf(m_run1 - mn1);
        m_run0 = mn0; m_run1 = mn1;
        float zs0 = 0.f, zs1 = 0.f;
#pragma unroll
        for (int ni = 0; ni < 16; ni++) {
            sacc[ni][0] = __expf(sacc[ni][0] - mn0);
            sacc[ni][1] = __expf(sacc[ni][1] - mn0);
            sacc[ni][2] = __expf(sacc[ni][2] - mn1);
            sacc[ni][3] = __expf(sacc[ni][3] - mn1);
            zs0 += sacc[ni][0] + sacc[ni][1];
            zs1 += sacc[ni][2] + sacc[ni][3];
        }
        zs0 += __shfl_xor_sync(0xffffffffu, zs0, 1);
        zs0 += __shfl_xor_sync(0xffffffffu, zs0, 2);
        zs1 += __shfl_xor_sync(0xffffffffu, zs1, 1);
        zs1 += __shfl_xor_sync(0xffffffffu, zs1, 2);
        z_run0 = z_run0 * fac0 + zs0;
        z_run1 = z_run1 * fac1 + zs1;
#pragma unroll
        for (int ni = 0; ni < 8; ni++) {
            oacc[ni][0] *= fac0; oacc[ni][1] *= fac0;
            oacc[ni][2] *= fac1; oacc[ni][3] *= fac1;
        }

#pragma unroll
        for (int ks = 0; ks < 8; ks++) {
            uint32_t ph[4], pl[4];
            packhl(sacc[2 * ks][0],     sacc[2 * ks][1],     ph[0], pl[0]);
            packhl(sacc[2 * ks][2],     sacc[2 * ks][3],     ph[1], pl[1]);
            packhl(sacc[2 * ks + 1][0], sacc[2 * ks + 1][1], ph[2], pl[2]);
            packhl(sacc[2 * ks + 1][2], sacc[2 * ks + 1][3], ph[3], pl[3]);
#pragma unroll
            for (int nj = 0; nj < 4; nj++) {
                uint32_t part = lane >> 3;
                uint32_t boff = ((uint32_t)(ks * 16 + (part & 1) * 8 + (lane & 7)) * PQ
                                 + nj * 16 + (part >> 1) * 8) * 2;
                uint32_t vhf[4], vlf[4];
                ldmx4t(vhf, vhB + boff);
                ldmx4t(vlf, vlB + boff);
                mma16816(oacc[nj * 2],     ph, vhf);
                mma16816(oacc[nj * 2],     ph, vlf);
                mma16816(oacc[nj * 2],     pl, vhf);
                mma16816(oacc[nj * 2 + 1], ph, vhf + 2);
                mma16816(oacc[nj * 2 + 1], ph, vlf + 2);
                mma16816(oacc[nj * 2 + 1], pl, vhf + 2);
            }
        }
    }

    float rz0 = 1.0f / z_run0, rz1 = 1.0f / z_run1;
    int r0 = q0 + wid * 16 + quad;
#pragma unroll
    for (int ni = 0; ni < 8; ni++) {
        int c = h * D + ni * 8 + qq * 2;
        *(float2*)&g_ao[(size_t)r0 * HID + c] =
            make_float2(oacc[ni][0] * rz0, oacc[ni][1] * rz0);
        *(float2*)&g_ao[(size_t)(r0 + 8) * HID + c] =
            make_float2(oacc[ni][2] * rz1, oacc[ni][3] * rz1);
    }
}

// ---------------- host ----------------
extern "C" void kernel_launch(void* const* d_in, const int* in_sizes, int n_in,
                              void* d_out, int out_size) {
    const float* x  = (const float*)d_in[0];
    const float* wq = (const float*)d_in[1];
    const float* wk = (const float*)d_in[2];
    const float* wv = (const float*)d_in[3];
    const float* wo = (const float*)d_in[4];
    float* out = (float*)d_out;

    static bool init_done = false;
    static void* ent_addr = nullptr;
    static void* infl_addr = nullptr;
    static cudaStream_t s2, s3;
    static cudaEvent_t evK, evB, evA, evSA;
    if (!init_done) {
        cudaFuncSetAttribute(attn2_mma_kernel,
                             cudaFuncAttributeMaxDynamicSharedMemorySize, ATTN2_SMEM);
        cudaFuncSetAttribute(qkv_mma_kernel,
                             cudaFuncAttributeMaxDynamicSharedMemorySize, GEMM_SMEM);
        cudaFuncSetAttribute(out_mma_kernel,
                             cudaFuncAttributeMaxDynamicSharedMemorySize, GEMM_SMEM);
        cudaFuncSetAttribute(scores_mma_kernel,
                             cudaFuncAttributeMaxDynamicSharedMemorySize, SCORE_SMEM);
        cudaGetSymbolAddress(&ent_addr, g_ent);
        cudaGetSymbolAddress(&infl_addr, g_infl);
        cudaStreamCreateWithFlags(&s2, cudaStreamNonBlocking);
        cudaStreamCreateWithFlags(&s3, cudaStreamNonBlocking);
        cudaEventCreateWithFlags(&evK, cudaEventDisableTiming);
        cudaEventCreateWithFlags(&evB, cudaEventDisableTiming);
        cudaEventCreateWithFlags(&evA, cudaEventDisableTiming);
        cudaEventCreateWithFlags(&evSA, cudaEventDisableTiming);
        init_done = true;
    }

    cudaMemsetAsync(ent_addr, 0, H * S * sizeof(float));
    cudaMemsetAsync(infl_addr, 0, H * S * sizeof(float));

    // main stream: Q,K projections
    qkv_mma_kernel<<<dim3(8, 16, 2), 256, GEMM_SMEM>>>(x, wq, wk, wv, 0);
    cudaEventRecord(evK, 0);

    // side stream s2: V projection + compression (overlaps scores chain)
    cudaStreamWaitEvent(s2, evK, 0);
    qkv_mma_kernel<<<dim3(8, 16, 1), 256, GEMM_SMEM, s2>>>(x, wq, wk, wv, 2);
    compress_kernel<<<dim3(16, 2), 256, 0, s2>>>();
    cudaEventRecord(evB, s2);

    // main: scores first half (h 0-7)
    scores_mma_kernel<<<dim3(16, 16, 8), 256, SCORE_SMEM>>>(0);
    cudaEventRecord(evA, 0);

    // s3: combine+stats for h 0-7 (DRAM-bound) overlaps scores_B (tensor-bound)
    cudaStreamWaitEvent(s3, evA, 0);
    combine_kernel<<<(8 * S) / 8, 256, 0, s3>>>(0);
    stats_kernel<<<dim3(16, 16, 8), 256, 0, s3>>>(0);
    cudaEventRecord(evSA, s3);

    // main: scores second half (h 8-15) + its combine/stats
    scores_mma_kernel<<<dim3(16, 16, 8), 256, SCORE_SMEM>>>(8);
    combine_kernel<<<(8 * S) / 8, 256>>>(8 * S);
    stats_kernel<<<dim3(16, 16, 8), 256>>>(8);

    // join stats halves -> importance/topk
    cudaStreamWaitEvent(0, evSA, 0);
    importance_kernel<<<8, 256>>>();
    topk_kernel<<<8, 256>>>();

    // join: gather needs topk + K,V; attn2 needs kcat/vcat + Q
    cudaStreamWaitEvent(0, evB, 0);
    gather_kernel<<<(H * KHH * D + 255) / 256, 256>>>();
    attn2_mma_kernel<<<dim3(S / 64, H), 128, ATTN2_SMEM>>>();
    out_mma_kernel<<<dim3(8, 16), 256, GEMM_SMEM>>>(wo, out);
}